// round 3
// baseline (speedup 1.0000x reference)
#include <cuda_runtime.h>
#include <math.h>

// Problem constants
#define Bn 4
#define Tn 2048
#define Cn 1024
#define Hn 16
#define Dn 64
#define Mrows (Bn * Tn)   // 8192

// Scratch (allocation-free: __device__ globals)
__device__ float g_q[Bn * Hn * Tn * Dn];   // [B,H,T,D]
__device__ float g_k[Bn * Hn * Tn * Dn];
__device__ float g_v[Bn * Hn * Tn * Dn];
__device__ float g_y[Mrows * Cn];          // attention output, [B*T, C]

// ---------------------------------------------------------------------------
// GEMM 1: qkv = x @ w_attn + b_attn, scattered into g_q/g_k/g_v [B,H,T,D]
// Tiles: 128x128x8, 256 threads, 8x8 per-thread microtile. Static smem only.
// ---------------------------------------------------------------------------
__global__ __launch_bounds__(256) void qkv_gemm_kernel(
    const float* __restrict__ x,      // [8192, 1024]
    const float* __restrict__ w,      // [1024, 3072]
    const float* __restrict__ bias)   // [3072]
{
    __shared__ float As[8][128];  // A transposed: As[k][m]
    __shared__ float Bs[8][128];  // Bs[k][n]

    const int K = Cn;
    const int N = 3 * Cn;

    int tid = threadIdx.x;
    int tx = tid & 15;
    int ty = tid >> 4;
    int bm = blockIdx.y * 128;
    int bn = blockIdx.x * 128;

    int arow = tid >> 1;
    int akg  = (tid & 1) * 4;
    int brow = tid >> 5;
    int bcol = (tid & 31) * 4;

    float acc[8][8];
    #pragma unroll
    for (int i = 0; i < 8; i++)
        #pragma unroll
        for (int j = 0; j < 8; j++) acc[i][j] = 0.f;

    for (int k0 = 0; k0 < K; k0 += 8) {
        float4 a4 = *(const float4*)&x[(size_t)(bm + arow) * K + k0 + akg];
        As[akg + 0][arow] = a4.x;
        As[akg + 1][arow] = a4.y;
        As[akg + 2][arow] = a4.z;
        As[akg + 3][arow] = a4.w;
        *(float4*)&Bs[brow][bcol] =
            *(const float4*)&w[(size_t)(k0 + brow) * N + bn + bcol];
        __syncthreads();

        #pragma unroll
        for (int kk = 0; kk < 8; kk++) {
            float a0[8], b0[8];
            *(float4*)&a0[0] = *(float4*)&As[kk][ty * 8];
            *(float4*)&a0[4] = *(float4*)&As[kk][ty * 8 + 4];
            *(float4*)&b0[0] = *(float4*)&Bs[kk][tx * 8];
            *(float4*)&b0[4] = *(float4*)&Bs[kk][tx * 8 + 4];
            #pragma unroll
            for (int i = 0; i < 8; i++)
                #pragma unroll
                for (int j = 0; j < 8; j++)
                    acc[i][j] += a0[i] * b0[j];
        }
        __syncthreads();
    }

    // Epilogue: bias + scatter to q/k/v in [B,H,T,D]
    #pragma unroll
    for (int i = 0; i < 8; i++) {
        int m = bm + ty * 8 + i;
        int b = m / Tn;
        int t = m - b * Tn;
        #pragma unroll
        for (int j = 0; j < 8; j++) {
            int n = bn + tx * 8 + j;
            float val = acc[i][j] + bias[n];
            int sec = n / Cn;
            int c = n - sec * Cn;
            int h = c >> 6;        // /64
            int d = c & 63;
            float* dst = (sec == 0) ? g_q : (sec == 1) ? g_k : g_v;
            dst[(((size_t)b * Hn + h) * Tn + t) * Dn + d] = val;
        }
    }
}

// ---------------------------------------------------------------------------
// Flash attention, fp32, static smem (<48KB).
// Block = 64 queries of one (b,h), key tiles of 32. 256 threads.
// Per-thread: 4q x 2k S-microtile, 4q x 4d O-microtile.
// Row stats via shfl over the 16-lane tx group.
// Strides MUST be multiples of 4 floats (16B) for float4 smem accesses.
// ---------------------------------------------------------------------------
#define QSTR 68   // stride for 64-wide rows (16B-aligned rows)
#define KSTR 36   // stride for 32-wide rows (16B-aligned rows)

__global__ __launch_bounds__(256) void attn_kernel()
{
    __shared__ float Qs[64 * QSTR];  // Qs[d][q]  (transposed), 17.4KB
    __shared__ float Ks[64 * KSTR];  // Ks[d][k]  (transposed), 9.2KB
    __shared__ float Vs[32 * QSTR];  // Vs[k][d],               8.7KB
    __shared__ float Ps[64 * KSTR];  // Ps[q][k],               9.2KB
    // total 44.5KB static

    int tid = threadIdx.x;
    int tx = tid & 15;
    int ty = tid >> 4;
    int bh = blockIdx.y;            // b*H + h
    int qt = blockIdx.x;
    int q0 = qt * 64;

    const float* qptr = g_q + (size_t)bh * Tn * Dn;
    const float* kptr = g_k + (size_t)bh * Tn * Dn;
    const float* vptr = g_v + (size_t)bh * Tn * Dn;

    // Load Q tile transposed: 64 rows x 64 d. Thread: row tid/4, 16 d-vals.
    {
        int r  = tid >> 2;
        int dg = (tid & 3) * 16;
        const float* src = qptr + (size_t)(q0 + r) * Dn + dg;
        #pragma unroll
        for (int u = 0; u < 4; u++) {
            float4 v4 = *(const float4*)(src + u * 4);
            Qs[(dg + u * 4 + 0) * QSTR + r] = v4.x;
            Qs[(dg + u * 4 + 1) * QSTR + r] = v4.y;
            Qs[(dg + u * 4 + 2) * QSTR + r] = v4.z;
            Qs[(dg + u * 4 + 3) * QSTR + r] = v4.w;
        }
    }

    float m_i[4], l_i[4], o[4][4];
    #pragma unroll
    for (int i = 0; i < 4; i++) {
        m_i[i] = -INFINITY;
        l_i[i] = 0.f;
        #pragma unroll
        for (int j = 0; j < 4; j++) o[i][j] = 0.f;
    }

    const float scale = 0.125f;  // 1/sqrt(64)
    const int n_ktiles = 2 * qt + 2;   // keys [0, q0+64) in tiles of 32

    for (int kt = 0; kt < n_ktiles; kt++) {
        int k0 = kt * 32;
        __syncthreads();  // protect Ks/Vs/Ps from previous iteration reads

        // Load K transposed + V natural: 32 rows x 64 d, 8 floats/thread
        {
            int r  = tid >> 3;          // 0..31
            int dg = (tid & 7) * 8;     // 0..56
            const float* srck = kptr + (size_t)(k0 + r) * Dn + dg;
            const float* srcv = vptr + (size_t)(k0 + r) * Dn + dg;
            #pragma unroll
            for (int u = 0; u < 2; u++) {
                float4 kv = *(const float4*)(srck + u * 4);
                Ks[(dg + u * 4 + 0) * KSTR + r] = kv.x;
                Ks[(dg + u * 4 + 1) * KSTR + r] = kv.y;
                Ks[(dg + u * 4 + 2) * KSTR + r] = kv.z;
                Ks[(dg + u * 4 + 3) * KSTR + r] = kv.w;
                *(float4*)&Vs[r * QSTR + dg + u * 4] =
                    *(const float4*)(srcv + u * 4);
            }
        }
        __syncthreads();

        // S = Q @ K^T  (4x2 per thread)
        float s[4][2];
        #pragma unroll
        for (int i = 0; i < 4; i++) { s[i][0] = 0.f; s[i][1] = 0.f; }

        #pragma unroll
        for (int d = 0; d < 64; d++) {
            float aq[4];
            *(float4*)aq = *(float4*)&Qs[d * QSTR + ty * 4];
            float2 bk = *(float2*)&Ks[d * KSTR + tx * 2];
            #pragma unroll
            for (int i = 0; i < 4; i++) {
                s[i][0] += aq[i] * bk.x;
                s[i][1] += aq[i] * bk.y;
            }
        }

        // Scale + causal mask (only tiles overlapping the diagonal)
        bool needs_mask = (k0 + 31 > q0);
        #pragma unroll
        for (int i = 0; i < 4; i++) {
            int q = q0 + ty * 4 + i;
            #pragma unroll
            for (int j = 0; j < 2; j++) {
                s[i][j] *= scale;
                if (needs_mask && (k0 + tx * 2 + j) > q) s[i][j] = -INFINITY;
            }
        }

        // Online softmax (row stats across the 16 tx lanes)
        #pragma unroll
        for (int i = 0; i < 4; i++) {
            float mt = fmaxf(s[i][0], s[i][1]);
            #pragma unroll
            for (int off = 1; off < 16; off <<= 1)
                mt = fmaxf(mt, __shfl_xor_sync(0xffffffffu, mt, off));
            float mnew = fmaxf(m_i[i], mt);
            float f = __expf(m_i[i] - mnew);
            m_i[i] = mnew;

            s[i][0] = __expf(s[i][0] - mnew);
            s[i][1] = __expf(s[i][1] - mnew);
            float rs = s[i][0] + s[i][1];
            #pragma unroll
            for (int off = 1; off < 16; off <<= 1)
                rs += __shfl_xor_sync(0xffffffffu, rs, off);

            l_i[i] = l_i[i] * f + rs;
            #pragma unroll
            for (int j = 0; j < 4; j++) o[i][j] *= f;
        }

        // Stage P to smem
        #pragma unroll
        for (int i = 0; i < 4; i++)
            *(float2*)&Ps[(ty * 4 + i) * KSTR + tx * 2] =
                make_float2(s[i][0], s[i][1]);
        __syncthreads();

        // O += P @ V
        #pragma unroll 8
        for (int k = 0; k < 32; k++) {
            float vv[4];
            *(float4*)vv = *(float4*)&Vs[k * QSTR + tx * 4];
            float pp[4];
            #pragma unroll
            for (int i = 0; i < 4; i++) pp[i] = Ps[(ty * 4 + i) * KSTR + k];
            #pragma unroll
            for (int i = 0; i < 4; i++)
                #pragma unroll
                for (int j = 0; j < 4; j++)
                    o[i][j] += pp[i] * vv[j];
        }
    }

    // Normalize and write to g_y [B*T, C] (head h occupies cols h*64..h*64+63)
    int b = bh / Hn;
    int h = bh - b * Hn;
    #pragma unroll
    for (int i = 0; i < 4; i++) {
        int t = q0 + ty * 4 + i;
        float inv = 1.f / l_i[i];
        float4 out4;
        out4.x = o[i][0] * inv;
        out4.y = o[i][1] * inv;
        out4.z = o[i][2] * inv;
        out4.w = o[i][3] * inv;
        *(float4*)&g_y[((size_t)(b * Tn + t)) * Cn + h * Dn + tx * 4] = out4;
    }
}

// ---------------------------------------------------------------------------
// GEMM 2: out = g_y @ w_proj + b_proj  -> d_out [8192, 1024]
// ---------------------------------------------------------------------------
__global__ __launch_bounds__(256) void proj_gemm_kernel(
    const float* __restrict__ w,     // [1024, 1024]
    const float* __restrict__ bias,  // [1024]
    float* __restrict__ out)         // [8192, 1024]
{
    __shared__ float As[8][128];
    __shared__ float Bs[8][128];

    const int K = Cn;
    const int N = Cn;

    int tid = threadIdx.x;
    int tx = tid & 15;
    int ty = tid >> 4;
    int bm = blockIdx.y * 128;
    int bn = blockIdx.x * 128;

    int arow = tid >> 1;
    int akg  = (tid & 1) * 4;
    int brow = tid >> 5;
    int bcol = (tid & 31) * 4;

    float acc[8][8];
    #pragma unroll
    for (int i = 0; i < 8; i++)
        #pragma unroll
        for (int j = 0; j < 8; j++) acc[i][j] = 0.f;

    for (int k0 = 0; k0 < K; k0 += 8) {
        float4 a4 = *(const float4*)&g_y[(size_t)(bm + arow) * K + k0 + akg];
        As[akg + 0][arow] = a4.x;
        As[akg + 1][arow] = a4.y;
        As[akg + 2][arow] = a4.z;
        As[akg + 3][arow] = a4.w;
        *(float4*)&Bs[brow][bcol] =
            *(const float4*)&w[(size_t)(k0 + brow) * N + bn + bcol];
        __syncthreads();

        #pragma unroll
        for (int kk = 0; kk < 8; kk++) {
            float a0[8], b0[8];
            *(float4*)&a0[0] = *(float4*)&As[kk][ty * 8];
            *(float4*)&a0[4] = *(float4*)&As[kk][ty * 8 + 4];
            *(float4*)&b0[0] = *(float4*)&Bs[kk][tx * 8];
            *(float4*)&b0[4] = *(float4*)&Bs[kk][tx * 8 + 4];
            #pragma unroll
            for (int i = 0; i < 8; i++)
                #pragma unroll
                for (int j = 0; j < 8; j++)
                    acc[i][j] += a0[i] * b0[j];
        }
        __syncthreads();
    }

    #pragma unroll
    for (int i = 0; i < 8; i++) {
        int m = bm + ty * 8 + i;
        #pragma unroll
        for (int j = 0; j < 8; j += 4) {
            int n = bn + tx * 8 + j;
            float4 v4;
            v4.x = acc[i][j + 0] + bias[n + 0];
            v4.y = acc[i][j + 1] + bias[n + 1];
            v4.z = acc[i][j + 2] + bias[n + 2];
            v4.w = acc[i][j + 3] + bias[n + 3];
            *(float4*)&out[(size_t)m * N + n] = v4;
        }
    }
}

// ---------------------------------------------------------------------------
// Launch: kernel launches ONLY — no other CUDA API calls.
// ---------------------------------------------------------------------------
extern "C" void kernel_launch(void* const* d_in, const int* in_sizes, int n_in,
                              void* d_out, int out_size)
{
    const float* x      = (const float*)d_in[0];  // [4,2048,1024]
    const float* w_attn = (const float*)d_in[1];  // [1024,3072]
    const float* b_attn = (const float*)d_in[2];  // [3072]
    const float* w_proj = (const float*)d_in[3];  // [1024,1024]
    const float* b_proj = (const float*)d_in[4];  // [1024]
    float* out = (float*)d_out;

    // 1) QKV GEMM: grid (N/128, M/128) = (24, 64)
    {
        dim3 grid(3 * Cn / 128, Mrows / 128);
        qkv_gemm_kernel<<<grid, 256>>>(x, w_attn, b_attn);
    }

    // 2) Attention: grid (T/64, B*H) = (32, 64)
    {
        dim3 grid(Tn / 64, Bn * Hn);
        attn_kernel<<<grid, 256>>>();
    }

    // 3) Projection GEMM: grid (N/128, M/128) = (8, 64)
    {
        dim3 grid(Cn / 128, Mrows / 128);
        proj_gemm_kernel<<<grid, 256>>>(w_proj, b_proj, out);
    }
}

// round 4
// speedup vs baseline: 1.6168x; 1.6168x over previous
#include <cuda_runtime.h>
#include <math.h>
#include <stdint.h>

// Problem constants
#define Bn 4
#define Tn 2048
#define Cn 1024
#define Hn 16
#define Dn 64
#define Mrows (Bn * Tn)   // 8192

// Scratch (allocation-free: __device__ globals)
__device__ float g_q[Bn * Hn * Tn * Dn];   // [B,H,T,D]
__device__ float g_k[Bn * Hn * Tn * Dn];
__device__ float g_v[Bn * Hn * Tn * Dn];
__device__ float g_y[Mrows * Cn];          // attention output, [B*T, C]

// ---------------------------------------------------------------------------
// tf32 helpers
// ---------------------------------------------------------------------------
__device__ __forceinline__ uint32_t f2tf32(float f) {
    uint32_t u;
    asm("cvt.rna.tf32.f32 %0, %1;" : "=r"(u) : "f"(f));
    return u;
}

__device__ __forceinline__ void mma_tf32(float* d, const uint32_t* a,
                                         const uint32_t* b) {
    asm volatile(
        "mma.sync.aligned.m16n8k8.row.col.f32.tf32.tf32.f32 "
        "{%0,%1,%2,%3}, {%4,%5,%6,%7}, {%8,%9}, {%0,%1,%2,%3};\n"
        : "+f"(d[0]), "+f"(d[1]), "+f"(d[2]), "+f"(d[3])
        : "r"(a[0]), "r"(a[1]), "r"(a[2]), "r"(a[3]),
          "r"(b[0]), "r"(b[1]));
}

// Smem stride: 136 floats. bank(k-row r, col c) = (r*8 + c) & 31 ->
// fragment loads (4 k-rows x 8 cols) hit 32 distinct banks.
#define GSTR 136

// ---------------------------------------------------------------------------
// GEMM 1 (tensor core tf32): qkv = x @ w_attn + b_attn -> g_q/g_k/g_v [B,H,T,D]
// CTA tile 128x128, K-step 16. 8 warps (2M x 4N), warp tile 64x32.
// ---------------------------------------------------------------------------
__global__ __launch_bounds__(256) void qkv_gemm_kernel(
    const float* __restrict__ x,      // [8192, 1024]
    const float* __restrict__ w,      // [1024, 3072]
    const float* __restrict__ bias)   // [3072]
{
    __shared__ uint32_t As[16][GSTR];  // As[k][m], tf32 bits
    __shared__ uint32_t Bs[16][GSTR];  // Bs[k][n], tf32 bits

    const int K = Cn;
    const int N = 3 * Cn;

    int tid  = threadIdx.x;
    int lane = tid & 31;
    int wid  = tid >> 5;
    int warpM = wid >> 2;   // 0..1
    int warpN = wid & 3;    // 0..3
    int bm = blockIdx.y * 128;
    int bn = blockIdx.x * 128;

    // A staging: row = tid/2, k-half = (tid&1)*8  (two float4 along k)
    int arow = tid >> 1;
    int akq  = (tid & 1) * 8;
    const float* aPtr = x + (size_t)(bm + arow) * K + akq;

    float4 aReg[2], bReg[2];
    aReg[0] = *(const float4*)(aPtr);
    aReg[1] = *(const float4*)(aPtr + 4);
    {
        int l0 = tid, l1 = tid + 256;
        bReg[0] = *(const float4*)&w[(size_t)(l0 >> 5) * N + bn + (l0 & 31) * 4];
        bReg[1] = *(const float4*)&w[(size_t)(l1 >> 5) * N + bn + (l1 & 31) * 4];
    }

    float acc[4][4][4];
    #pragma unroll
    for (int i = 0; i < 4; i++)
        #pragma unroll
        for (int j = 0; j < 4; j++)
            #pragma unroll
            for (int r = 0; r < 4; r++) acc[i][j][r] = 0.f;

    for (int k0 = 0; k0 < K; k0 += 16) {
        __syncthreads();
        // Store staged tiles to smem (fp32 -> tf32)
        {
            float av[8] = {aReg[0].x, aReg[0].y, aReg[0].z, aReg[0].w,
                           aReg[1].x, aReg[1].y, aReg[1].z, aReg[1].w};
            #pragma unroll
            for (int j = 0; j < 8; j++) As[akq + j][arow] = f2tf32(av[j]);
        }
        {
            int l0 = tid, l1 = tid + 256;
            uint4 u0 = make_uint4(f2tf32(bReg[0].x), f2tf32(bReg[0].y),
                                  f2tf32(bReg[0].z), f2tf32(bReg[0].w));
            uint4 u1 = make_uint4(f2tf32(bReg[1].x), f2tf32(bReg[1].y),
                                  f2tf32(bReg[1].z), f2tf32(bReg[1].w));
            *(uint4*)&Bs[l0 >> 5][(l0 & 31) * 4] = u0;
            *(uint4*)&Bs[l1 >> 5][(l1 & 31) * 4] = u1;
        }
        __syncthreads();

        // Prefetch next K-tile
        if (k0 + 16 < K) {
            aReg[0] = *(const float4*)(aPtr + k0 + 16);
            aReg[1] = *(const float4*)(aPtr + k0 + 20);
            int l0 = tid, l1 = tid + 256;
            bReg[0] = *(const float4*)&w[(size_t)(k0 + 16 + (l0 >> 5)) * N + bn + (l0 & 31) * 4];
            bReg[1] = *(const float4*)&w[(size_t)(k0 + 16 + (l1 >> 5)) * N + bn + (l1 & 31) * 4];
        }

        // Compute: two k8 steps
        #pragma unroll
        for (int kk = 0; kk < 16; kk += 8) {
            uint32_t a[4][4], b[4][2];
            #pragma unroll
            for (int mf = 0; mf < 4; mf++) {
                int m = warpM * 64 + mf * 16 + (lane >> 2);
                a[mf][0] = As[kk + (lane & 3)][m];
                a[mf][1] = As[kk + (lane & 3)][m + 8];
                a[mf][2] = As[kk + 4 + (lane & 3)][m];
                a[mf][3] = As[kk + 4 + (lane & 3)][m + 8];
            }
            #pragma unroll
            for (int nf = 0; nf < 4; nf++) {
                int n = warpN * 32 + nf * 8 + (lane >> 2);
                b[nf][0] = Bs[kk + (lane & 3)][n];
                b[nf][1] = Bs[kk + 4 + (lane & 3)][n];
            }
            #pragma unroll
            for (int mf = 0; mf < 4; mf++)
                #pragma unroll
                for (int nf = 0; nf < 4; nf++)
                    mma_tf32(acc[mf][nf], a[mf], b[nf]);
        }
    }

    // Epilogue: bias + scatter to q/k/v in [B,H,T,D]
    #pragma unroll
    for (int mf = 0; mf < 4; mf++) {
        #pragma unroll
        for (int nf = 0; nf < 4; nf++) {
            #pragma unroll
            for (int r = 0; r < 4; r++) {
                int m = bm + warpM * 64 + mf * 16 + (lane >> 2) + (r >> 1) * 8;
                int n = bn + warpN * 32 + nf * 8 + (lane & 3) * 2 + (r & 1);
                float val = acc[mf][nf][r] + bias[n];
                int b = m >> 11;           // /2048
                int t = m & 2047;
                int sec = n >> 10;         // /1024
                int c = n & 1023;
                int h = c >> 6;
                int d = c & 63;
                float* dst = (sec == 0) ? g_q : (sec == 1) ? g_k : g_v;
                dst[(((size_t)b * Hn + h) * Tn + t) * Dn + d] = val;
            }
        }
    }
}

// ---------------------------------------------------------------------------
// GEMM 2 (tensor core tf32): out = g_y @ w_proj + b_proj -> [8192, 1024]
// ---------------------------------------------------------------------------
__global__ __launch_bounds__(256) void proj_gemm_kernel(
    const float* __restrict__ w,     // [1024, 1024]
    const float* __restrict__ bias,  // [1024]
    float* __restrict__ out)         // [8192, 1024]
{
    __shared__ uint32_t As[16][GSTR];
    __shared__ uint32_t Bs[16][GSTR];

    const int K = Cn;
    const int N = Cn;

    int tid  = threadIdx.x;
    int lane = tid & 31;
    int wid  = tid >> 5;
    int warpM = wid >> 2;
    int warpN = wid & 3;
    int bm = blockIdx.y * 128;
    int bn = blockIdx.x * 128;

    int arow = tid >> 1;
    int akq  = (tid & 1) * 8;
    const float* aPtr = g_y + (size_t)(bm + arow) * K + akq;

    float4 aReg[2], bReg[2];
    aReg[0] = *(const float4*)(aPtr);
    aReg[1] = *(const float4*)(aPtr + 4);
    {
        int l0 = tid, l1 = tid + 256;
        bReg[0] = *(const float4*)&w[(size_t)(l0 >> 5) * N + bn + (l0 & 31) * 4];
        bReg[1] = *(const float4*)&w[(size_t)(l1 >> 5) * N + bn + (l1 & 31) * 4];
    }

    float acc[4][4][4];
    #pragma unroll
    for (int i = 0; i < 4; i++)
        #pragma unroll
        for (int j = 0; j < 4; j++)
            #pragma unroll
            for (int r = 0; r < 4; r++) acc[i][j][r] = 0.f;

    for (int k0 = 0; k0 < K; k0 += 16) {
        __syncthreads();
        {
            float av[8] = {aReg[0].x, aReg[0].y, aReg[0].z, aReg[0].w,
                           aReg[1].x, aReg[1].y, aReg[1].z, aReg[1].w};
            #pragma unroll
            for (int j = 0; j < 8; j++) As[akq + j][arow] = f2tf32(av[j]);
        }
        {
            int l0 = tid, l1 = tid + 256;
            uint4 u0 = make_uint4(f2tf32(bReg[0].x), f2tf32(bReg[0].y),
                                  f2tf32(bReg[0].z), f2tf32(bReg[0].w));
            uint4 u1 = make_uint4(f2tf32(bReg[1].x), f2tf32(bReg[1].y),
                                  f2tf32(bReg[1].z), f2tf32(bReg[1].w));
            *(uint4*)&Bs[l0 >> 5][(l0 & 31) * 4] = u0;
            *(uint4*)&Bs[l1 >> 5][(l1 & 31) * 4] = u1;
        }
        __syncthreads();

        if (k0 + 16 < K) {
            aReg[0] = *(const float4*)(aPtr + k0 + 16);
            aReg[1] = *(const float4*)(aPtr + k0 + 20);
            int l0 = tid, l1 = tid + 256;
            bReg[0] = *(const float4*)&w[(size_t)(k0 + 16 + (l0 >> 5)) * N + bn + (l0 & 31) * 4];
            bReg[1] = *(const float4*)&w[(size_t)(k0 + 16 + (l1 >> 5)) * N + bn + (l1 & 31) * 4];
        }

        #pragma unroll
        for (int kk = 0; kk < 16; kk += 8) {
            uint32_t a[4][4], b[4][2];
            #pragma unroll
            for (int mf = 0; mf < 4; mf++) {
                int m = warpM * 64 + mf * 16 + (lane >> 2);
                a[mf][0] = As[kk + (lane & 3)][m];
                a[mf][1] = As[kk + (lane & 3)][m + 8];
                a[mf][2] = As[kk + 4 + (lane & 3)][m];
                a[mf][3] = As[kk + 4 + (lane & 3)][m + 8];
            }
            #pragma unroll
            for (int nf = 0; nf < 4; nf++) {
                int n = warpN * 32 + nf * 8 + (lane >> 2);
                b[nf][0] = Bs[kk + (lane & 3)][n];
                b[nf][1] = Bs[kk + 4 + (lane & 3)][n];
            }
            #pragma unroll
            for (int mf = 0; mf < 4; mf++)
                #pragma unroll
                for (int nf = 0; nf < 4; nf++)
                    mma_tf32(acc[mf][nf], a[mf], b[nf]);
        }
    }

    // Epilogue: bias + float2 stores (c0,c1 are adjacent columns)
    #pragma unroll
    for (int mf = 0; mf < 4; mf++) {
        #pragma unroll
        for (int nf = 0; nf < 4; nf++) {
            int n = bn + warpN * 32 + nf * 8 + (lane & 3) * 2;
            float bx = bias[n], by = bias[n + 1];
            #pragma unroll
            for (int half = 0; half < 2; half++) {
                int m = bm + warpM * 64 + mf * 16 + (lane >> 2) + half * 8;
                float2 v2;
                v2.x = acc[mf][nf][half * 2 + 0] + bx;
                v2.y = acc[mf][nf][half * 2 + 1] + by;
                *(float2*)&out[(size_t)m * N + n] = v2;
            }
        }
    }
}

// ---------------------------------------------------------------------------
// Flash attention, fp32, static smem (<48KB). (unchanged from R2)
// ---------------------------------------------------------------------------
#define QSTR 68
#define KSTR 36

__global__ __launch_bounds__(256) void attn_kernel()
{
    __shared__ float Qs[64 * QSTR];  // Qs[d][q]  (transposed)
    __shared__ float Ks[64 * KSTR];  // Ks[d][k]  (transposed)
    __shared__ float Vs[32 * QSTR];  // Vs[k][d]
    __shared__ float Ps[64 * KSTR];  // Ps[q][k]

    int tid = threadIdx.x;
    int tx = tid & 15;
    int ty = tid >> 4;
    int bh = blockIdx.y;
    int qt = blockIdx.x;
    int q0 = qt * 64;

    const float* qptr = g_q + (size_t)bh * Tn * Dn;
    const float* kptr = g_k + (size_t)bh * Tn * Dn;
    const float* vptr = g_v + (size_t)bh * Tn * Dn;

    {
        int r  = tid >> 2;
        int dg = (tid & 3) * 16;
        const float* src = qptr + (size_t)(q0 + r) * Dn + dg;
        #pragma unroll
        for (int u = 0; u < 4; u++) {
            float4 v4 = *(const float4*)(src + u * 4);
            Qs[(dg + u * 4 + 0) * QSTR + r] = v4.x;
            Qs[(dg + u * 4 + 1) * QSTR + r] = v4.y;
            Qs[(dg + u * 4 + 2) * QSTR + r] = v4.z;
            Qs[(dg + u * 4 + 3) * QSTR + r] = v4.w;
        }
    }

    float m_i[4], l_i[4], o[4][4];
    #pragma unroll
    for (int i = 0; i < 4; i++) {
        m_i[i] = -INFINITY;
        l_i[i] = 0.f;
        #pragma unroll
        for (int j = 0; j < 4; j++) o[i][j] = 0.f;
    }

    const float scale = 0.125f;
    const int n_ktiles = 2 * qt + 2;

    for (int kt = 0; kt < n_ktiles; kt++) {
        int k0 = kt * 32;
        __syncthreads();

        {
            int r  = tid >> 3;
            int dg = (tid & 7) * 8;
            const float* srck = kptr + (size_t)(k0 + r) * Dn + dg;
            const float* srcv = vptr + (size_t)(k0 + r) * Dn + dg;
            #pragma unroll
            for (int u = 0; u < 2; u++) {
                float4 kv = *(const float4*)(srck + u * 4);
                Ks[(dg + u * 4 + 0) * KSTR + r] = kv.x;
                Ks[(dg + u * 4 + 1) * KSTR + r] = kv.y;
                Ks[(dg + u * 4 + 2) * KSTR + r] = kv.z;
                Ks[(dg + u * 4 + 3) * KSTR + r] = kv.w;
                *(float4*)&Vs[r * QSTR + dg + u * 4] =
                    *(const float4*)(srcv + u * 4);
            }
        }
        __syncthreads();

        float s[4][2];
        #pragma unroll
        for (int i = 0; i < 4; i++) { s[i][0] = 0.f; s[i][1] = 0.f; }

        #pragma unroll
        for (int d = 0; d < 64; d++) {
            float aq[4];
            *(float4*)aq = *(float4*)&Qs[d * QSTR + ty * 4];
            float2 bk = *(float2*)&Ks[d * KSTR + tx * 2];
            #pragma unroll
            for (int i = 0; i < 4; i++) {
                s[i][0] += aq[i] * bk.x;
                s[i][1] += aq[i] * bk.y;
            }
        }

        bool needs_mask = (k0 + 31 > q0);
        #pragma unroll
        for (int i = 0; i < 4; i++) {
            int q = q0 + ty * 4 + i;
            #pragma unroll
            for (int j = 0; j < 2; j++) {
                s[i][j] *= scale;
                if (needs_mask && (k0 + tx * 2 + j) > q) s[i][j] = -INFINITY;
            }
        }

        #pragma unroll
        for (int i = 0; i < 4; i++) {
            float mt = fmaxf(s[i][0], s[i][1]);
            #pragma unroll
            for (int off = 1; off < 16; off <<= 1)
                mt = fmaxf(mt, __shfl_xor_sync(0xffffffffu, mt, off));
            float mnew = fmaxf(m_i[i], mt);
            float f = __expf(m_i[i] - mnew);
            m_i[i] = mnew;

            s[i][0] = __expf(s[i][0] - mnew);
            s[i][1] = __expf(s[i][1] - mnew);
            float rs = s[i][0] + s[i][1];
            #pragma unroll
            for (int off = 1; off < 16; off <<= 1)
                rs += __shfl_xor_sync(0xffffffffu, rs, off);

            l_i[i] = l_i[i] * f + rs;
            #pragma unroll
            for (int j = 0; j < 4; j++) o[i][j] *= f;
        }

        #pragma unroll
        for (int i = 0; i < 4; i++)
            *(float2*)&Ps[(ty * 4 + i) * KSTR + tx * 2] =
                make_float2(s[i][0], s[i][1]);
        __syncthreads();

        #pragma unroll 8
        for (int k = 0; k < 32; k++) {
            float vv[4];
            *(float4*)vv = *(float4*)&Vs[k * QSTR + tx * 4];
            float pp[4];
            #pragma unroll
            for (int i = 0; i < 4; i++) pp[i] = Ps[(ty * 4 + i) * KSTR + k];
            #pragma unroll
            for (int i = 0; i < 4; i++)
                #pragma unroll
                for (int j = 0; j < 4; j++)
                    o[i][j] += pp[i] * vv[j];
        }
    }

    int b = bh / Hn;
    int h = bh - b * Hn;
    #pragma unroll
    for (int i = 0; i < 4; i++) {
        int t = q0 + ty * 4 + i;
        float inv = 1.f / l_i[i];
        float4 out4;
        out4.x = o[i][0] * inv;
        out4.y = o[i][1] * inv;
        out4.z = o[i][2] * inv;
        out4.w = o[i][3] * inv;
        *(float4*)&g_y[((size_t)(b * Tn + t)) * Cn + h * Dn + tx * 4] = out4;
    }
}

// ---------------------------------------------------------------------------
// Launch: kernel launches ONLY — no other CUDA API calls.
// ---------------------------------------------------------------------------
extern "C" void kernel_launch(void* const* d_in, const int* in_sizes, int n_in,
                              void* d_out, int out_size)
{
    const float* x      = (const float*)d_in[0];
    const float* w_attn = (const float*)d_in[1];
    const float* b_attn = (const float*)d_in[2];
    const float* w_proj = (const float*)d_in[3];
    const float* b_proj = (const float*)d_in[4];
    float* out = (float*)d_out;

    {
        dim3 grid(3 * Cn / 128, Mrows / 128);
        qkv_gemm_kernel<<<grid, 256>>>(x, w_attn, b_attn);
    }
    {
        dim3 grid(Tn / 64, Bn * Hn);
        attn_kernel<<<grid, 256>>>();
    }
    {
        dim3 grid(Cn / 128, Mrows / 128);
        proj_gemm_kernel<<<grid, 256>>>(w_proj, b_proj, out);
    }
}

// round 5
// speedup vs baseline: 2.5943x; 1.6046x over previous
#include <cuda_runtime.h>
#include <math.h>
#include <stdint.h>

// Problem constants
#define Bn 4
#define Tn 2048
#define Cn 1024
#define Hn 16
#define Dn 64
#define Mrows (Bn * Tn)   // 8192

// Scratch (allocation-free: __device__ globals)
__device__ float g_q[Bn * Hn * Tn * Dn];   // [B,H,T,D]
__device__ float g_k[Bn * Hn * Tn * Dn];
__device__ float g_v[Bn * Hn * Tn * Dn];
__device__ float g_y[Mrows * Cn];          // attention output, [B*T, C]

// ---------------------------------------------------------------------------
// tf32 helpers
// ---------------------------------------------------------------------------
__device__ __forceinline__ uint32_t f2tf32(float f) {
    uint32_t u;
    asm("cvt.rna.tf32.f32 %0, %1;" : "=r"(u) : "f"(f));
    return u;
}

__device__ __forceinline__ void mma_tf32(float* d, const uint32_t* a,
                                         const uint32_t* b) {
    asm volatile(
        "mma.sync.aligned.m16n8k8.row.col.f32.tf32.tf32.f32 "
        "{%0,%1,%2,%3}, {%4,%5,%6,%7}, {%8,%9}, {%0,%1,%2,%3};\n"
        : "+f"(d[0]), "+f"(d[1]), "+f"(d[2]), "+f"(d[3])
        : "r"(a[0]), "r"(a[1]), "r"(a[2]), "r"(a[3]),
          "r"(b[0]), "r"(b[1]));
}

#define GSTR 136

// ---------------------------------------------------------------------------
// GEMM 1 (tensor core tf32): qkv = x @ w_attn + b_attn -> g_q/g_k/g_v [B,H,T,D]
// ---------------------------------------------------------------------------
__global__ __launch_bounds__(256) void qkv_gemm_kernel(
    const float* __restrict__ x,      // [8192, 1024]
    const float* __restrict__ w,      // [1024, 3072]
    const float* __restrict__ bias)   // [3072]
{
    __shared__ uint32_t As[16][GSTR];
    __shared__ uint32_t Bs[16][GSTR];

    const int K = Cn;
    const int N = 3 * Cn;

    int tid  = threadIdx.x;
    int lane = tid & 31;
    int wid  = tid >> 5;
    int warpM = wid >> 2;
    int warpN = wid & 3;
    int bm = blockIdx.y * 128;
    int bn = blockIdx.x * 128;

    int arow = tid >> 1;
    int akq  = (tid & 1) * 8;
    const float* aPtr = x + (size_t)(bm + arow) * K + akq;

    float4 aReg[2], bReg[2];
    aReg[0] = *(const float4*)(aPtr);
    aReg[1] = *(const float4*)(aPtr + 4);
    {
        int l0 = tid, l1 = tid + 256;
        bReg[0] = *(const float4*)&w[(size_t)(l0 >> 5) * N + bn + (l0 & 31) * 4];
        bReg[1] = *(const float4*)&w[(size_t)(l1 >> 5) * N + bn + (l1 & 31) * 4];
    }

    float acc[4][4][4];
    #pragma unroll
    for (int i = 0; i < 4; i++)
        #pragma unroll
        for (int j = 0; j < 4; j++)
            #pragma unroll
            for (int r = 0; r < 4; r++) acc[i][j][r] = 0.f;

    for (int k0 = 0; k0 < K; k0 += 16) {
        __syncthreads();
        {
            float av[8] = {aReg[0].x, aReg[0].y, aReg[0].z, aReg[0].w,
                           aReg[1].x, aReg[1].y, aReg[1].z, aReg[1].w};
            #pragma unroll
            for (int j = 0; j < 8; j++) As[akq + j][arow] = f2tf32(av[j]);
        }
        {
            int l0 = tid, l1 = tid + 256;
            uint4 u0 = make_uint4(f2tf32(bReg[0].x), f2tf32(bReg[0].y),
                                  f2tf32(bReg[0].z), f2tf32(bReg[0].w));
            uint4 u1 = make_uint4(f2tf32(bReg[1].x), f2tf32(bReg[1].y),
                                  f2tf32(bReg[1].z), f2tf32(bReg[1].w));
            *(uint4*)&Bs[l0 >> 5][(l0 & 31) * 4] = u0;
            *(uint4*)&Bs[l1 >> 5][(l1 & 31) * 4] = u1;
        }
        __syncthreads();

        if (k0 + 16 < K) {
            aReg[0] = *(const float4*)(aPtr + k0 + 16);
            aReg[1] = *(const float4*)(aPtr + k0 + 20);
            int l0 = tid, l1 = tid + 256;
            bReg[0] = *(const float4*)&w[(size_t)(k0 + 16 + (l0 >> 5)) * N + bn + (l0 & 31) * 4];
            bReg[1] = *(const float4*)&w[(size_t)(k0 + 16 + (l1 >> 5)) * N + bn + (l1 & 31) * 4];
        }

        #pragma unroll
        for (int kk = 0; kk < 16; kk += 8) {
            uint32_t a[4][4], b[4][2];
            #pragma unroll
            for (int mf = 0; mf < 4; mf++) {
                int m = warpM * 64 + mf * 16 + (lane >> 2);
                a[mf][0] = As[kk + (lane & 3)][m];
                a[mf][1] = As[kk + (lane & 3)][m + 8];
                a[mf][2] = As[kk + 4 + (lane & 3)][m];
                a[mf][3] = As[kk + 4 + (lane & 3)][m + 8];
            }
            #pragma unroll
            for (int nf = 0; nf < 4; nf++) {
                int n = warpN * 32 + nf * 8 + (lane >> 2);
                b[nf][0] = Bs[kk + (lane & 3)][n];
                b[nf][1] = Bs[kk + 4 + (lane & 3)][n];
            }
            #pragma unroll
            for (int mf = 0; mf < 4; mf++)
                #pragma unroll
                for (int nf = 0; nf < 4; nf++)
                    mma_tf32(acc[mf][nf], a[mf], b[nf]);
        }
    }

    #pragma unroll
    for (int mf = 0; mf < 4; mf++) {
        #pragma unroll
        for (int nf = 0; nf < 4; nf++) {
            #pragma unroll
            for (int r = 0; r < 4; r++) {
                int m = bm + warpM * 64 + mf * 16 + (lane >> 2) + (r >> 1) * 8;
                int n = bn + warpN * 32 + nf * 8 + (lane & 3) * 2 + (r & 1);
                float val = acc[mf][nf][r] + bias[n];
                int b = m >> 11;
                int t = m & 2047;
                int sec = n >> 10;
                int c = n & 1023;
                int h = c >> 6;
                int d = c & 63;
                float* dst = (sec == 0) ? g_q : (sec == 1) ? g_k : g_v;
                dst[(((size_t)b * Hn + h) * Tn + t) * Dn + d] = val;
            }
        }
    }
}

// ---------------------------------------------------------------------------
// GEMM 2 (tensor core tf32): out = g_y @ w_proj + b_proj -> [8192, 1024]
// ---------------------------------------------------------------------------
__global__ __launch_bounds__(256) void proj_gemm_kernel(
    const float* __restrict__ w,
    const float* __restrict__ bias,
    float* __restrict__ out)
{
    __shared__ uint32_t As[16][GSTR];
    __shared__ uint32_t Bs[16][GSTR];

    const int K = Cn;
    const int N = Cn;

    int tid  = threadIdx.x;
    int lane = tid & 31;
    int wid  = tid >> 5;
    int warpM = wid >> 2;
    int warpN = wid & 3;
    int bm = blockIdx.y * 128;
    int bn = blockIdx.x * 128;

    int arow = tid >> 1;
    int akq  = (tid & 1) * 8;
    const float* aPtr = g_y + (size_t)(bm + arow) * K + akq;

    float4 aReg[2], bReg[2];
    aReg[0] = *(const float4*)(aPtr);
    aReg[1] = *(const float4*)(aPtr + 4);
    {
        int l0 = tid, l1 = tid + 256;
        bReg[0] = *(const float4*)&w[(size_t)(l0 >> 5) * N + bn + (l0 & 31) * 4];
        bReg[1] = *(const float4*)&w[(size_t)(l1 >> 5) * N + bn + (l1 & 31) * 4];
    }

    float acc[4][4][4];
    #pragma unroll
    for (int i = 0; i < 4; i++)
        #pragma unroll
        for (int j = 0; j < 4; j++)
            #pragma unroll
            for (int r = 0; r < 4; r++) acc[i][j][r] = 0.f;

    for (int k0 = 0; k0 < K; k0 += 16) {
        __syncthreads();
        {
            float av[8] = {aReg[0].x, aReg[0].y, aReg[0].z, aReg[0].w,
                           aReg[1].x, aReg[1].y, aReg[1].z, aReg[1].w};
            #pragma unroll
            for (int j = 0; j < 8; j++) As[akq + j][arow] = f2tf32(av[j]);
        }
        {
            int l0 = tid, l1 = tid + 256;
            uint4 u0 = make_uint4(f2tf32(bReg[0].x), f2tf32(bReg[0].y),
                                  f2tf32(bReg[0].z), f2tf32(bReg[0].w));
            uint4 u1 = make_uint4(f2tf32(bReg[1].x), f2tf32(bReg[1].y),
                                  f2tf32(bReg[1].z), f2tf32(bReg[1].w));
            *(uint4*)&Bs[l0 >> 5][(l0 & 31) * 4] = u0;
            *(uint4*)&Bs[l1 >> 5][(l1 & 31) * 4] = u1;
        }
        __syncthreads();

        if (k0 + 16 < K) {
            aReg[0] = *(const float4*)(aPtr + k0 + 16);
            aReg[1] = *(const float4*)(aPtr + k0 + 20);
            int l0 = tid, l1 = tid + 256;
            bReg[0] = *(const float4*)&w[(size_t)(k0 + 16 + (l0 >> 5)) * N + bn + (l0 & 31) * 4];
            bReg[1] = *(const float4*)&w[(size_t)(k0 + 16 + (l1 >> 5)) * N + bn + (l1 & 31) * 4];
        }

        #pragma unroll
        for (int kk = 0; kk < 16; kk += 8) {
            uint32_t a[4][4], b[4][2];
            #pragma unroll
            for (int mf = 0; mf < 4; mf++) {
                int m = warpM * 64 + mf * 16 + (lane >> 2);
                a[mf][0] = As[kk + (lane & 3)][m];
                a[mf][1] = As[kk + (lane & 3)][m + 8];
                a[mf][2] = As[kk + 4 + (lane & 3)][m];
                a[mf][3] = As[kk + 4 + (lane & 3)][m + 8];
            }
            #pragma unroll
            for (int nf = 0; nf < 4; nf++) {
                int n = warpN * 32 + nf * 8 + (lane >> 2);
                b[nf][0] = Bs[kk + (lane & 3)][n];
                b[nf][1] = Bs[kk + 4 + (lane & 3)][n];
            }
            #pragma unroll
            for (int mf = 0; mf < 4; mf++)
                #pragma unroll
                for (int nf = 0; nf < 4; nf++)
                    mma_tf32(acc[mf][nf], a[mf], b[nf]);
        }
    }

    #pragma unroll
    for (int mf = 0; mf < 4; mf++) {
        #pragma unroll
        for (int nf = 0; nf < 4; nf++) {
            int n = bn + warpN * 32 + nf * 8 + (lane & 3) * 2;
            float bx = bias[n], by = bias[n + 1];
            #pragma unroll
            for (int half = 0; half < 2; half++) {
                int m = bm + warpM * 64 + mf * 16 + (lane >> 2) + half * 8;
                float2 v2;
                v2.x = acc[mf][nf][half * 2 + 0] + bx;
                v2.y = acc[mf][nf][half * 2 + 1] + by;
                *(float2*)&out[(size_t)m * N + n] = v2;
            }
        }
    }
}

// ---------------------------------------------------------------------------
// Flash attention on tf32 tensor cores.
// Block: 128 threads (4 warps), 64 queries of one (b,h); warp owns 16 queries.
// Key tiles of 32. S = Q@K^T and O += P@V via mma.m16n8k8.
// Smem strides 68/36 -> conflict-free fragment LDS (bank = 4r+j).
// ---------------------------------------------------------------------------
#define AQS 68   // stride for 64-wide (d) rows
#define AVS 36   // stride for 32-wide (key) rows

__global__ __launch_bounds__(128) void attn_kernel()
{
    __shared__ uint32_t Qs[64 * AQS];  // [q][d]   tf32 (scale folded in), 17.4KB
    __shared__ uint32_t Ks[32 * AQS];  // [key][d] tf32,                    8.7KB
    __shared__ uint32_t Vt[64 * AVS];  // [d][key] tf32,                    9.2KB
    __shared__ uint32_t Ps[64 * AVS];  // [q][key] tf32, warp-private rows, 9.2KB

    int tid  = threadIdx.x;
    int lane = tid & 31;
    int w    = tid >> 5;        // warp 0..3
    int bh = blockIdx.y;
    int qt = blockIdx.x;
    int q0 = qt * 64;

    const float* qptr = g_q + (size_t)bh * Tn * Dn;
    const float* kptr = g_k + (size_t)bh * Tn * Dn;
    const float* vptr = g_v + (size_t)bh * Tn * Dn;

    // Load Q tile [64 x 64], fold in softmax scale 1/8, cvt tf32.
    {
        int r  = tid >> 1;
        int cb = (tid & 1) * 32;
        const float* src = qptr + (size_t)(q0 + r) * Dn + cb;
        #pragma unroll
        for (int u = 0; u < 8; u++) {
            float4 v4 = *(const float4*)(src + u * 4);
            Qs[r * AQS + cb + u * 4 + 0] = f2tf32(v4.x * 0.125f);
            Qs[r * AQS + cb + u * 4 + 1] = f2tf32(v4.y * 0.125f);
            Qs[r * AQS + cb + u * 4 + 2] = f2tf32(v4.z * 0.125f);
            Qs[r * AQS + cb + u * 4 + 3] = f2tf32(v4.w * 0.125f);
        }
    }

    float m_i[2] = {-1e30f, -1e30f};
    float l_i[2] = {0.f, 0.f};
    float o[8][4];
    #pragma unroll
    for (int nf = 0; nf < 8; nf++)
        #pragma unroll
        for (int r = 0; r < 4; r++) o[nf][r] = 0.f;

    const int rq = lane >> 2;       // 0..7
    const int cj = lane & 3;        // 0..3
    const int qrow = w * 16;        // warp's local query base
    const int n_ktiles = 2 * qt + 2;

    for (int kt = 0; kt < n_ktiles; kt++) {
        int k0 = kt * 32;
        __syncthreads();   // prior reads of Ks/Vt complete

        // Load K [32 x 64] natural; V [32 x 64] transposed -> Vt[d][key]
        {
            int r  = tid >> 2;          // 0..31
            int cb = (tid & 3) * 16;    // 0..48
            const float* srck = kptr + (size_t)(k0 + r) * Dn + cb;
            const float* srcv = vptr + (size_t)(k0 + r) * Dn + cb;
            #pragma unroll
            for (int u = 0; u < 4; u++) {
                float4 kv = *(const float4*)(srck + u * 4);
                Ks[r * AQS + cb + u * 4 + 0] = f2tf32(kv.x);
                Ks[r * AQS + cb + u * 4 + 1] = f2tf32(kv.y);
                Ks[r * AQS + cb + u * 4 + 2] = f2tf32(kv.z);
                Ks[r * AQS + cb + u * 4 + 3] = f2tf32(kv.w);
                float4 vv = *(const float4*)(srcv + u * 4);
                Vt[(cb + u * 4 + 0) * AVS + r] = f2tf32(vv.x);
                Vt[(cb + u * 4 + 1) * AVS + r] = f2tf32(vv.y);
                Vt[(cb + u * 4 + 2) * AVS + r] = f2tf32(vv.z);
                Vt[(cb + u * 4 + 3) * AVS + r] = f2tf32(vv.w);
            }
        }
        __syncthreads();

        // ---- S = Q @ K^T : per warp 16x32, 4 n-frags, 8 k-steps ----
        float s[4][4];
        #pragma unroll
        for (int nf = 0; nf < 4; nf++)
            #pragma unroll
            for (int r = 0; r < 4; r++) s[nf][r] = 0.f;

        #pragma unroll
        for (int kk = 0; kk < 8; kk++) {
            int kc = kk * 8;
            uint32_t a[4];
            a[0] = Qs[(qrow + rq) * AQS + kc + cj];
            a[1] = Qs[(qrow + rq + 8) * AQS + kc + cj];
            a[2] = Qs[(qrow + rq) * AQS + kc + cj + 4];
            a[3] = Qs[(qrow + rq + 8) * AQS + kc + cj + 4];
            #pragma unroll
            for (int nf = 0; nf < 4; nf++) {
                uint32_t b[2];
                b[0] = Ks[(nf * 8 + rq) * AQS + kc + cj];
                b[1] = Ks[(nf * 8 + rq) * AQS + kc + cj + 4];
                mma_tf32(s[nf], a, b);
            }
        }

        // ---- causal mask ----
        int rowA = q0 + qrow + rq;
        int rowB = rowA + 8;
        if (k0 + 31 > q0 + qrow) {
            #pragma unroll
            for (int nf = 0; nf < 4; nf++) {
                int col = k0 + nf * 8 + cj * 2;
                if (col > rowA)     s[nf][0] = -1e30f;
                if (col + 1 > rowA) s[nf][1] = -1e30f;
                if (col > rowB)     s[nf][2] = -1e30f;
                if (col + 1 > rowB) s[nf][3] = -1e30f;
            }
        }

        // ---- online softmax (rows rA = c0/c1, rB = c2/c3) ----
        {
            float mtA = fmaxf(fmaxf(s[0][0], s[0][1]), fmaxf(s[1][0], s[1][1]));
            mtA = fmaxf(mtA, fmaxf(fmaxf(s[2][0], s[2][1]), fmaxf(s[3][0], s[3][1])));
            float mtB = fmaxf(fmaxf(s[0][2], s[0][3]), fmaxf(s[1][2], s[1][3]));
            mtB = fmaxf(mtB, fmaxf(fmaxf(s[2][2], s[2][3]), fmaxf(s[3][2], s[3][3])));
            #pragma unroll
            for (int off = 1; off < 4; off <<= 1) {
                mtA = fmaxf(mtA, __shfl_xor_sync(0xffffffffu, mtA, off));
                mtB = fmaxf(mtB, __shfl_xor_sync(0xffffffffu, mtB, off));
            }
            float mnA = fmaxf(m_i[0], mtA);
            float mnB = fmaxf(m_i[1], mtB);
            float fA = __expf(m_i[0] - mnA);
            float fB = __expf(m_i[1] - mnB);
            m_i[0] = mnA; m_i[1] = mnB;

            float rsA = 0.f, rsB = 0.f;
            #pragma unroll
            for (int nf = 0; nf < 4; nf++) {
                s[nf][0] = __expf(s[nf][0] - mnA);
                s[nf][1] = __expf(s[nf][1] - mnA);
                s[nf][2] = __expf(s[nf][2] - mnB);
                s[nf][3] = __expf(s[nf][3] - mnB);
                rsA += s[nf][0] + s[nf][1];
                rsB += s[nf][2] + s[nf][3];
            }
            #pragma unroll
            for (int off = 1; off < 4; off <<= 1) {
                rsA += __shfl_xor_sync(0xffffffffu, rsA, off);
                rsB += __shfl_xor_sync(0xffffffffu, rsB, off);
            }
            l_i[0] = l_i[0] * fA + rsA;
            l_i[1] = l_i[1] * fB + rsB;
            #pragma unroll
            for (int nf = 0; nf < 8; nf++) {
                o[nf][0] *= fA; o[nf][1] *= fA;
                o[nf][2] *= fB; o[nf][3] *= fB;
            }
        }

        // ---- stage P to warp-private smem rows ----
        #pragma unroll
        for (int nf = 0; nf < 4; nf++) {
            int col = nf * 8 + cj * 2;
            Ps[(qrow + rq) * AVS + col]     = f2tf32(s[nf][0]);
            Ps[(qrow + rq) * AVS + col + 1] = f2tf32(s[nf][1]);
            Ps[(qrow + rq + 8) * AVS + col]     = f2tf32(s[nf][2]);
            Ps[(qrow + rq + 8) * AVS + col + 1] = f2tf32(s[nf][3]);
        }
        __syncwarp();

        // ---- O += P @ V : 8 n-frags (d), 4 k-steps (key) ----
        #pragma unroll
        for (int kk = 0; kk < 4; kk++) {
            int kc = kk * 8;
            uint32_t a[4];
            a[0] = Ps[(qrow + rq) * AVS + kc + cj];
            a[1] = Ps[(qrow + rq + 8) * AVS + kc + cj];
            a[2] = Ps[(qrow + rq) * AVS + kc + cj + 4];
            a[3] = Ps[(qrow + rq + 8) * AVS + kc + cj + 4];
            #pragma unroll
            for (int nf = 0; nf < 8; nf++) {
                uint32_t b[2];
                b[0] = Vt[(nf * 8 + rq) * AVS + kc + cj];
                b[1] = Vt[(nf * 8 + rq) * AVS + kc + cj + 4];
                mma_tf32(o[nf], a, b);
            }
        }
        __syncwarp();  // Ps reads done before next-iter overwrite
    }

    // ---- epilogue: normalize, write g_y [B*T, C] ----
    int b = bh >> 4;
    int h = bh & 15;
    float invA = 1.f / l_i[0];
    float invB = 1.f / l_i[1];
    int tA = q0 + qrow + rq;
    int tB = tA + 8;
    #pragma unroll
    for (int nf = 0; nf < 8; nf++) {
        int d = h * Dn + nf * 8 + cj * 2;
        float2 vA = make_float2(o[nf][0] * invA, o[nf][1] * invA);
        float2 vB = make_float2(o[nf][2] * invB, o[nf][3] * invB);
        *(float2*)&g_y[((size_t)(b * Tn + tA)) * Cn + d] = vA;
        *(float2*)&g_y[((size_t)(b * Tn + tB)) * Cn + d] = vB;
    }
}

// ---------------------------------------------------------------------------
// Launch: kernel launches ONLY.
// ---------------------------------------------------------------------------
extern "C" void kernel_launch(void* const* d_in, const int* in_sizes, int n_in,
                              void* d_out, int out_size)
{
    const float* x      = (const float*)d_in[0];
    const float* w_attn = (const float*)d_in[1];
    const float* b_attn = (const float*)d_in[2];
    const float* w_proj = (const float*)d_in[3];
    const float* b_proj = (const float*)d_in[4];
    float* out = (float*)d_out;

    {
        dim3 grid(3 * Cn / 128, Mrows / 128);
        qkv_gemm_kernel<<<grid, 256>>>(x, w_attn, b_attn);
    }
    {
        dim3 grid(Tn / 64, Bn * Hn);
        attn_kernel<<<grid, 128>>>();
    }
    {
        dim3 grid(Cn / 128, Mrows / 128);
        proj_gemm_kernel<<<grid, 256>>>(w_proj, b_proj, out);
    }
}

// round 6
// speedup vs baseline: 3.0430x; 1.1730x over previous
#include <cuda_runtime.h>
#include <math.h>
#include <stdint.h>

// Problem constants
#define Bn 4
#define Tn 2048
#define Cn 1024
#define Hn 16
#define Dn 64
#define Mrows (Bn * Tn)   // 8192

// Scratch (allocation-free: __device__ globals)
__device__ float g_q[Bn * Hn * Tn * Dn];   // [B,H,T,D] fp32
__device__ float g_k[Bn * Hn * Tn * Dn];   // [B,H,T,D] tf32 bits
__device__ float g_v[Bn * Hn * Tn * Dn];   // [B,H,D,T] tf32 bits (TRANSPOSED)
__device__ float g_y[Mrows * Cn];          // attention output, [B*T, C]

// ---------------------------------------------------------------------------
// tf32 helpers
// ---------------------------------------------------------------------------
__device__ __forceinline__ uint32_t f2tf32(float f) {
    uint32_t u;
    asm("cvt.rna.tf32.f32 %0, %1;" : "=r"(u) : "f"(f));
    return u;
}

__device__ __forceinline__ void mma_tf32(float* d, const uint32_t* a,
                                         const uint32_t* b) {
    asm volatile(
        "mma.sync.aligned.m16n8k8.row.col.f32.tf32.tf32.f32 "
        "{%0,%1,%2,%3}, {%4,%5,%6,%7}, {%8,%9}, {%0,%1,%2,%3};\n"
        : "+f"(d[0]), "+f"(d[1]), "+f"(d[2]), "+f"(d[3])
        : "r"(a[0]), "r"(a[1]), "r"(a[2]), "r"(a[3]),
          "r"(b[0]), "r"(b[1]));
}

#define GSTR 136

// ---------------------------------------------------------------------------
// GEMM 1 (tensor core tf32): qkv = x @ w_attn + b_attn
// Epilogue: Q plain fp32 [B,H,T,D]; K tf32 bits [B,H,T,D]; V tf32 bits [B,H,D,T]
// ---------------------------------------------------------------------------
__global__ __launch_bounds__(256) void qkv_gemm_kernel(
    const float* __restrict__ x,      // [8192, 1024]
    const float* __restrict__ w,      // [1024, 3072]
    const float* __restrict__ bias)   // [3072]
{
    __shared__ uint32_t As[16][GSTR];
    __shared__ uint32_t Bs[16][GSTR];

    const int K = Cn;
    const int N = 3 * Cn;

    int tid  = threadIdx.x;
    int lane = tid & 31;
    int wid  = tid >> 5;
    int warpM = wid >> 2;
    int warpN = wid & 3;
    int bm = blockIdx.y * 128;
    int bn = blockIdx.x * 128;

    int arow = tid >> 1;
    int akq  = (tid & 1) * 8;
    const float* aPtr = x + (size_t)(bm + arow) * K + akq;

    float4 aReg[2], bReg[2];
    aReg[0] = *(const float4*)(aPtr);
    aReg[1] = *(const float4*)(aPtr + 4);
    {
        int l0 = tid, l1 = tid + 256;
        bReg[0] = *(const float4*)&w[(size_t)(l0 >> 5) * N + bn + (l0 & 31) * 4];
        bReg[1] = *(const float4*)&w[(size_t)(l1 >> 5) * N + bn + (l1 & 31) * 4];
    }

    float acc[4][4][4];
    #pragma unroll
    for (int i = 0; i < 4; i++)
        #pragma unroll
        for (int j = 0; j < 4; j++)
            #pragma unroll
            for (int r = 0; r < 4; r++) acc[i][j][r] = 0.f;

    for (int k0 = 0; k0 < K; k0 += 16) {
        __syncthreads();
        {
            float av[8] = {aReg[0].x, aReg[0].y, aReg[0].z, aReg[0].w,
                           aReg[1].x, aReg[1].y, aReg[1].z, aReg[1].w};
            #pragma unroll
            for (int j = 0; j < 8; j++) As[akq + j][arow] = f2tf32(av[j]);
        }
        {
            int l0 = tid, l1 = tid + 256;
            uint4 u0 = make_uint4(f2tf32(bReg[0].x), f2tf32(bReg[0].y),
                                  f2tf32(bReg[0].z), f2tf32(bReg[0].w));
            uint4 u1 = make_uint4(f2tf32(bReg[1].x), f2tf32(bReg[1].y),
                                  f2tf32(bReg[1].z), f2tf32(bReg[1].w));
            *(uint4*)&Bs[l0 >> 5][(l0 & 31) * 4] = u0;
            *(uint4*)&Bs[l1 >> 5][(l1 & 31) * 4] = u1;
        }
        __syncthreads();

        if (k0 + 16 < K) {
            aReg[0] = *(const float4*)(aPtr + k0 + 16);
            aReg[1] = *(const float4*)(aPtr + k0 + 20);
            int l0 = tid, l1 = tid + 256;
            bReg[0] = *(const float4*)&w[(size_t)(k0 + 16 + (l0 >> 5)) * N + bn + (l0 & 31) * 4];
            bReg[1] = *(const float4*)&w[(size_t)(k0 + 16 + (l1 >> 5)) * N + bn + (l1 & 31) * 4];
        }

        #pragma unroll
        for (int kk = 0; kk < 16; kk += 8) {
            uint32_t a[4][4], b[4][2];
            #pragma unroll
            for (int mf = 0; mf < 4; mf++) {
                int m = warpM * 64 + mf * 16 + (lane >> 2);
                a[mf][0] = As[kk + (lane & 3)][m];
                a[mf][1] = As[kk + (lane & 3)][m + 8];
                a[mf][2] = As[kk + 4 + (lane & 3)][m];
                a[mf][3] = As[kk + 4 + (lane & 3)][m + 8];
            }
            #pragma unroll
            for (int nf = 0; nf < 4; nf++) {
                int n = warpN * 32 + nf * 8 + (lane >> 2);
                b[nf][0] = Bs[kk + (lane & 3)][n];
                b[nf][1] = Bs[kk + 4 + (lane & 3)][n];
            }
            #pragma unroll
            for (int mf = 0; mf < 4; mf++)
                #pragma unroll
                for (int nf = 0; nf < 4; nf++)
                    mma_tf32(acc[mf][nf], a[mf], b[nf]);
        }
    }

    #pragma unroll
    for (int mf = 0; mf < 4; mf++) {
        #pragma unroll
        for (int nf = 0; nf < 4; nf++) {
            #pragma unroll
            for (int r = 0; r < 4; r++) {
                int m = bm + warpM * 64 + mf * 16 + (lane >> 2) + (r >> 1) * 8;
                int n = bn + warpN * 32 + nf * 8 + (lane & 3) * 2 + (r & 1);
                float val = acc[mf][nf][r] + bias[n];
                int b = m >> 11;
                int t = m & 2047;
                int sec = n >> 10;
                int c = n & 1023;
                int h = c >> 6;
                int d = c & 63;
                if (sec == 0) {
                    g_q[(((size_t)b * Hn + h) * Tn + t) * Dn + d] = val;
                } else if (sec == 1) {
                    g_k[(((size_t)b * Hn + h) * Tn + t) * Dn + d] =
                        __uint_as_float(f2tf32(val));
                } else {
                    // V transposed: [B,H,D,T]
                    g_v[(((size_t)b * Hn + h) * Dn + d) * Tn + t] =
                        __uint_as_float(f2tf32(val));
                }
            }
        }
    }
}

// ---------------------------------------------------------------------------
// GEMM 2 (tensor core tf32): out = g_y @ w_proj + b_proj -> [8192, 1024]
// ---------------------------------------------------------------------------
__global__ __launch_bounds__(256) void proj_gemm_kernel(
    const float* __restrict__ w,
    const float* __restrict__ bias,
    float* __restrict__ out)
{
    __shared__ uint32_t As[16][GSTR];
    __shared__ uint32_t Bs[16][GSTR];

    const int K = Cn;
    const int N = Cn;

    int tid  = threadIdx.x;
    int lane = tid & 31;
    int wid  = tid >> 5;
    int warpM = wid >> 2;
    int warpN = wid & 3;
    int bm = blockIdx.y * 128;
    int bn = blockIdx.x * 128;

    int arow = tid >> 1;
    int akq  = (tid & 1) * 8;
    const float* aPtr = g_y + (size_t)(bm + arow) * K + akq;

    float4 aReg[2], bReg[2];
    aReg[0] = *(const float4*)(aPtr);
    aReg[1] = *(const float4*)(aPtr + 4);
    {
        int l0 = tid, l1 = tid + 256;
        bReg[0] = *(const float4*)&w[(size_t)(l0 >> 5) * N + bn + (l0 & 31) * 4];
        bReg[1] = *(const float4*)&w[(size_t)(l1 >> 5) * N + bn + (l1 & 31) * 4];
    }

    float acc[4][4][4];
    #pragma unroll
    for (int i = 0; i < 4; i++)
        #pragma unroll
        for (int j = 0; j < 4; j++)
            #pragma unroll
            for (int r = 0; r < 4; r++) acc[i][j][r] = 0.f;

    for (int k0 = 0; k0 < K; k0 += 16) {
        __syncthreads();
        {
            float av[8] = {aReg[0].x, aReg[0].y, aReg[0].z, aReg[0].w,
                           aReg[1].x, aReg[1].y, aReg[1].z, aReg[1].w};
            #pragma unroll
            for (int j = 0; j < 8; j++) As[akq + j][arow] = f2tf32(av[j]);
        }
        {
            int l0 = tid, l1 = tid + 256;
            uint4 u0 = make_uint4(f2tf32(bReg[0].x), f2tf32(bReg[0].y),
                                  f2tf32(bReg[0].z), f2tf32(bReg[0].w));
            uint4 u1 = make_uint4(f2tf32(bReg[1].x), f2tf32(bReg[1].y),
                                  f2tf32(bReg[1].z), f2tf32(bReg[1].w));
            *(uint4*)&Bs[l0 >> 5][(l0 & 31) * 4] = u0;
            *(uint4*)&Bs[l1 >> 5][(l1 & 31) * 4] = u1;
        }
        __syncthreads();

        if (k0 + 16 < K) {
            aReg[0] = *(const float4*)(aPtr + k0 + 16);
            aReg[1] = *(const float4*)(aPtr + k0 + 20);
            int l0 = tid, l1 = tid + 256;
            bReg[0] = *(const float4*)&w[(size_t)(k0 + 16 + (l0 >> 5)) * N + bn + (l0 & 31) * 4];
            bReg[1] = *(const float4*)&w[(size_t)(k0 + 16 + (l1 >> 5)) * N + bn + (l1 & 31) * 4];
        }

        #pragma unroll
        for (int kk = 0; kk < 16; kk += 8) {
            uint32_t a[4][4], b[4][2];
            #pragma unroll
            for (int mf = 0; mf < 4; mf++) {
                int m = warpM * 64 + mf * 16 + (lane >> 2);
                a[mf][0] = As[kk + (lane & 3)][m];
                a[mf][1] = As[kk + (lane & 3)][m + 8];
                a[mf][2] = As[kk + 4 + (lane & 3)][m];
                a[mf][3] = As[kk + 4 + (lane & 3)][m + 8];
            }
            #pragma unroll
            for (int nf = 0; nf < 4; nf++) {
                int n = warpN * 32 + nf * 8 + (lane >> 2);
                b[nf][0] = Bs[kk + (lane & 3)][n];
                b[nf][1] = Bs[kk + 4 + (lane & 3)][n];
            }
            #pragma unroll
            for (int mf = 0; mf < 4; mf++)
                #pragma unroll
                for (int nf = 0; nf < 4; nf++)
                    mma_tf32(acc[mf][nf], a[mf], b[nf]);
        }
    }

    #pragma unroll
    for (int mf = 0; mf < 4; mf++) {
        #pragma unroll
        for (int nf = 0; nf < 4; nf++) {
            int n = bn + warpN * 32 + nf * 8 + (lane & 3) * 2;
            float bx = bias[n], by = bias[n + 1];
            #pragma unroll
            for (int half = 0; half < 2; half++) {
                int m = bm + warpM * 64 + mf * 16 + (lane >> 2) + half * 8;
                float2 v2;
                v2.x = acc[mf][nf][half * 2 + 0] + bx;
                v2.y = acc[mf][nf][half * 2 + 1] + by;
                *(float2*)&out[(size_t)m * N + n] = v2;
            }
        }
    }
}

// ---------------------------------------------------------------------------
// Flash attention, tf32 tensor cores, Q register-resident.
// Block: 128 threads (4 warps), 128 queries of one (b,h); warp owns 32 queries.
// Key tiles of 32. K arrives as tf32 bits [t][d]; V as tf32 bits [d][t].
// Strides: Ks 68, Vt/Ps 36 -> conflict-free fragment LDS (bank = 4*rq+cj).
// ---------------------------------------------------------------------------
#define AKS 68
#define APS 36

__global__ __launch_bounds__(128) void attn_kernel()
{
    __shared__ uint32_t Ks[32 * AKS];   // [key][d]  8.7KB
    __shared__ uint32_t Vt[64 * APS];   // [d][key]  9.2KB
    __shared__ uint32_t Ps[128 * APS];  // [q][key] 18.4KB (warp-private rows)

    int tid  = threadIdx.x;
    int lane = tid & 31;
    int w    = tid >> 5;
    int bh = blockIdx.y;
    int qt = blockIdx.x;
    int q0 = qt * 128;

    const float* qptr = g_q + (size_t)bh * Tn * Dn;
    const uint32_t* kptr = (const uint32_t*)(g_k) + (size_t)bh * Tn * Dn;
    const uint32_t* vtptr = (const uint32_t*)(g_v) + (size_t)bh * Dn * Tn;

    const int rq = lane >> 2;     // 0..7
    const int cj = lane & 3;      // 0..3
    const int qrow = w * 32;      // warp's local query base

    // ---- Q fragments register-resident (scale folded), one-time load ----
    uint32_t qa[8][2][4];
    #pragma unroll
    for (int kk = 0; kk < 8; kk++) {
        int kc = kk * 8 + cj;
        #pragma unroll
        for (int mf = 0; mf < 2; mf++) {
            const float* qr = qptr + (size_t)(q0 + qrow + mf * 16 + rq) * Dn;
            qa[kk][mf][0] = f2tf32(qr[kc] * 0.125f);
            qa[kk][mf][1] = f2tf32(qr[8 * Dn + kc] * 0.125f);
            qa[kk][mf][2] = f2tf32(qr[kc + 4] * 0.125f);
            qa[kk][mf][3] = f2tf32(qr[8 * Dn + kc + 4] * 0.125f);
        }
    }

    float m_i[2][2], l_i[2][2];
    float o[2][8][4];
    #pragma unroll
    for (int mf = 0; mf < 2; mf++) {
        m_i[mf][0] = -1e30f; m_i[mf][1] = -1e30f;
        l_i[mf][0] = 0.f;    l_i[mf][1] = 0.f;
        #pragma unroll
        for (int nf = 0; nf < 8; nf++)
            #pragma unroll
            for (int r = 0; r < 4; r++) o[mf][nf][r] = 0.f;
    }

    const int n_ktiles = 4 * qt + 4;   // keys [0, q0+128)

    for (int kt = 0; kt < n_ktiles; kt++) {
        int k0 = kt * 32;
        __syncthreads();   // prior Ks/Vt reads complete

        // Load K tile [32 x 64] (pure uint4 copy, already tf32)
        {
            int r  = tid >> 2;
            int cb = (tid & 3) * 16;
            const uint32_t* src = kptr + (size_t)(k0 + r) * Dn + cb;
            #pragma unroll
            for (int u = 0; u < 4; u++)
                *(uint4*)&Ks[r * AKS + cb + u * 4] = *(const uint4*)(src + u * 4);
        }
        // Load V tile transposed [64 x 32] (pure uint4 copy from [d][t] layout)
        {
            int r  = tid >> 1;
            int cb = (tid & 1) * 16;
            const uint32_t* src = vtptr + (size_t)r * Tn + k0 + cb;
            #pragma unroll
            for (int u = 0; u < 4; u++)
                *(uint4*)&Vt[r * APS + cb + u * 4] = *(const uint4*)(src + u * 4);
        }
        __syncthreads();

        // ---- S = Q @ K^T : warp 32x32, A from registers ----
        float s[2][4][4];
        #pragma unroll
        for (int mf = 0; mf < 2; mf++)
            #pragma unroll
            for (int nf = 0; nf < 4; nf++)
                #pragma unroll
                for (int r = 0; r < 4; r++) s[mf][nf][r] = 0.f;

        #pragma unroll
        for (int kk = 0; kk < 8; kk++) {
            int kc = kk * 8;
            #pragma unroll
            for (int nf = 0; nf < 4; nf++) {
                uint32_t b[2];
                b[0] = Ks[(nf * 8 + rq) * AKS + kc + cj];
                b[1] = Ks[(nf * 8 + rq) * AKS + kc + cj + 4];
                mma_tf32(s[0][nf], qa[kk][0], b);
                mma_tf32(s[1][nf], qa[kk][1], b);
            }
        }

        // ---- causal mask ----
        #pragma unroll
        for (int mf = 0; mf < 2; mf++) {
            int rowA = q0 + qrow + mf * 16 + rq;
            int rowB = rowA + 8;
            if (k0 + 31 > q0 + qrow + mf * 16) {
                #pragma unroll
                for (int nf = 0; nf < 4; nf++) {
                    int col = k0 + nf * 8 + cj * 2;
                    if (col > rowA)     s[mf][nf][0] = -1e30f;
                    if (col + 1 > rowA) s[mf][nf][1] = -1e30f;
                    if (col > rowB)     s[mf][nf][2] = -1e30f;
                    if (col + 1 > rowB) s[mf][nf][3] = -1e30f;
                }
            }
        }

        // ---- online softmax per mf (rows A=c0/c1, B=c2/c3) ----
        #pragma unroll
        for (int mf = 0; mf < 2; mf++) {
            float mtA = fmaxf(fmaxf(s[mf][0][0], s[mf][0][1]),
                              fmaxf(s[mf][1][0], s[mf][1][1]));
            mtA = fmaxf(mtA, fmaxf(fmaxf(s[mf][2][0], s[mf][2][1]),
                                   fmaxf(s[mf][3][0], s[mf][3][1])));
            float mtB = fmaxf(fmaxf(s[mf][0][2], s[mf][0][3]),
                              fmaxf(s[mf][1][2], s[mf][1][3]));
            mtB = fmaxf(mtB, fmaxf(fmaxf(s[mf][2][2], s[mf][2][3]),
                                   fmaxf(s[mf][3][2], s[mf][3][3])));
            #pragma unroll
            for (int off = 1; off < 4; off <<= 1) {
                mtA = fmaxf(mtA, __shfl_xor_sync(0xffffffffu, mtA, off));
                mtB = fmaxf(mtB, __shfl_xor_sync(0xffffffffu, mtB, off));
            }
            float mnA = fmaxf(m_i[mf][0], mtA);
            float mnB = fmaxf(m_i[mf][1], mtB);
            float fA = __expf(m_i[mf][0] - mnA);
            float fB = __expf(m_i[mf][1] - mnB);
            m_i[mf][0] = mnA; m_i[mf][1] = mnB;

            float rsA = 0.f, rsB = 0.f;
            #pragma unroll
            for (int nf = 0; nf < 4; nf++) {
                s[mf][nf][0] = __expf(s[mf][nf][0] - mnA);
                s[mf][nf][1] = __expf(s[mf][nf][1] - mnA);
                s[mf][nf][2] = __expf(s[mf][nf][2] - mnB);
                s[mf][nf][3] = __expf(s[mf][nf][3] - mnB);
                rsA += s[mf][nf][0] + s[mf][nf][1];
                rsB += s[mf][nf][2] + s[mf][nf][3];
            }
            #pragma unroll
            for (int off = 1; off < 4; off <<= 1) {
                rsA += __shfl_xor_sync(0xffffffffu, rsA, off);
                rsB += __shfl_xor_sync(0xffffffffu, rsB, off);
            }
            l_i[mf][0] = l_i[mf][0] * fA + rsA;
            l_i[mf][1] = l_i[mf][1] * fB + rsB;
            #pragma unroll
            for (int nf = 0; nf < 8; nf++) {
                o[mf][nf][0] *= fA; o[mf][nf][1] *= fA;
                o[mf][nf][2] *= fB; o[mf][nf][3] *= fB;
            }
        }

        // ---- stage P to warp-private smem rows ----
        #pragma unroll
        for (int mf = 0; mf < 2; mf++) {
            int rA = qrow + mf * 16 + rq;
            #pragma unroll
            for (int nf = 0; nf < 4; nf++) {
                int col = nf * 8 + cj * 2;
                Ps[rA * APS + col]           = f2tf32(s[mf][nf][0]);
                Ps[rA * APS + col + 1]       = f2tf32(s[mf][nf][1]);
                Ps[(rA + 8) * APS + col]     = f2tf32(s[mf][nf][2]);
                Ps[(rA + 8) * APS + col + 1] = f2tf32(s[mf][nf][3]);
            }
        }
        __syncwarp();

        // ---- O += P @ V : 8 n-frags (d), 4 k-steps (key) ----
        #pragma unroll
        for (int kk = 0; kk < 4; kk++) {
            int kc = kk * 8;
            uint32_t a[2][4];
            #pragma unroll
            for (int mf = 0; mf < 2; mf++) {
                int rA = qrow + mf * 16 + rq;
                a[mf][0] = Ps[rA * APS + kc + cj];
                a[mf][1] = Ps[(rA + 8) * APS + kc + cj];
                a[mf][2] = Ps[rA * APS + kc + cj + 4];
                a[mf][3] = Ps[(rA + 8) * APS + kc + cj + 4];
            }
            #pragma unroll
            for (int nf = 0; nf < 8; nf++) {
                uint32_t b[2];
                b[0] = Vt[(nf * 8 + rq) * APS + kc + cj];
                b[1] = Vt[(nf * 8 + rq) * APS + kc + cj + 4];
                mma_tf32(o[0][nf], a[0], b);
                mma_tf32(o[1][nf], a[1], b);
            }
        }
        __syncwarp();  // Ps reads done before next-iter overwrite
    }

    // ---- epilogue: normalize, write g_y [B*T, C] ----
    int b = bh >> 4;
    int h = bh & 15;
    #pragma unroll
    for (int mf = 0; mf < 2; mf++) {
        float invA = 1.f / l_i[mf][0];
        float invB = 1.f / l_i[mf][1];
        int tA = q0 + qrow + mf * 16 + rq;
        int tB = tA + 8;
        #pragma unroll
        for (int nf = 0; nf < 8; nf++) {
            int d = h * Dn + nf * 8 + cj * 2;
            float2 vA = make_float2(o[mf][nf][0] * invA, o[mf][nf][1] * invA);
            float2 vB = make_float2(o[mf][nf][2] * invB, o[mf][nf][3] * invB);
            *(float2*)&g_y[((size_t)(b * Tn + tA)) * Cn + d] = vA;
            *(float2*)&g_y[((size_t)(b * Tn + tB)) * Cn + d] = vB;
        }
    }
}

// ---------------------------------------------------------------------------
// Launch: kernel launches ONLY.
// ---------------------------------------------------------------------------
extern "C" void kernel_launch(void* const* d_in, const int* in_sizes, int n_in,
                              void* d_out, int out_size)
{
    const float* x      = (const float*)d_in[0];
    const float* w_attn = (const float*)d_in[1];
    const float* b_attn = (const float*)d_in[2];
    const float* w_proj = (const float*)d_in[3];
    const float* b_proj = (const float*)d_in[4];
    float* out = (float*)d_out;

    {
        dim3 grid(3 * Cn / 128, Mrows / 128);
        qkv_gemm_kernel<<<grid, 256>>>(x, w_attn, b_attn);
    }
    {
        dim3 grid(Tn / 128, Bn * Hn);
        attn_kernel<<<grid, 128>>>();
    }
    {
        dim3 grid(Cn / 128, Mrows / 128);
        proj_gemm_kernel<<<grid, 256>>>(w_proj, b_proj, out);
    }
}

// round 8
// speedup vs baseline: 3.8755x; 1.2736x over previous
#include <cuda_runtime.h>
#include <cuda_fp16.h>
#include <math.h>
#include <stdint.h>

// Problem constants
#define Bn 4
#define Tn 2048
#define Cn 1024
#define Hn 16
#define Dn 64
#define Mrows (Bn * Tn)   // 8192

// Scratch (allocation-free: __device__ globals)
__device__ float g_q[Bn * Hn * Tn * Dn];   // [B,H,T,D] fp32
__device__ float g_k[Bn * Hn * Tn * Dn];   // [B,H,T,D] tf32 bits
__device__ float g_v[Bn * Hn * Tn * Dn];   // [B,H,D,T] tf32 bits (TRANSPOSED)
__device__ float g_y[Mrows * Cn];          // attention output, [B*T, C]

// ---------------------------------------------------------------------------
// helpers
// ---------------------------------------------------------------------------
__device__ __forceinline__ uint32_t f2tf32(float f) {
    uint32_t u;
    asm("cvt.rna.tf32.f32 %0, %1;" : "=r"(u) : "f"(f));
    return u;
}

__device__ __forceinline__ uint32_t f2h2(float x, float y) {
    __half2 h = __floats2half2_rn(x, y);
    return *(uint32_t*)&h;
}

__device__ __forceinline__ void mma_tf32(float* d, const uint32_t* a,
                                         const uint32_t* b) {
    asm volatile(
        "mma.sync.aligned.m16n8k8.row.col.f32.tf32.tf32.f32 "
        "{%0,%1,%2,%3}, {%4,%5,%6,%7}, {%8,%9}, {%0,%1,%2,%3};\n"
        : "+f"(d[0]), "+f"(d[1]), "+f"(d[2]), "+f"(d[3])
        : "r"(a[0]), "r"(a[1]), "r"(a[2]), "r"(a[3]),
          "r"(b[0]), "r"(b[1]));
}

__device__ __forceinline__ void mma_f16(float* d, const uint32_t* a,
                                        const uint32_t* b) {
    asm volatile(
        "mma.sync.aligned.m16n8k16.row.col.f32.f16.f16.f32 "
        "{%0,%1,%2,%3}, {%4,%5,%6,%7}, {%8,%9}, {%0,%1,%2,%3};\n"
        : "+f"(d[0]), "+f"(d[1]), "+f"(d[2]), "+f"(d[3])
        : "r"(a[0]), "r"(a[1]), "r"(a[2]), "r"(a[3]),
          "r"(b[0]), "r"(b[1]));
}

#define GSTR 136

// ---------------------------------------------------------------------------
// GEMM 1 (fp16 tensor core): qkv = x @ w_attn + b_attn
// Smem: half2 k-pairs, 8 k2-rows per K16 tile. Frag LDS bank = 8*cj+rq (free).
// Epilogue: Q fp32 [B,H,T,D]; K tf32 bits [B,H,T,D]; V tf32 bits [B,H,D,T].
// ---------------------------------------------------------------------------
__global__ __launch_bounds__(256) void qkv_gemm_kernel(
    const float* __restrict__ x,      // [8192, 1024]
    const float* __restrict__ w,      // [1024, 3072]
    const float* __restrict__ bias)   // [3072]
{
    __shared__ uint32_t As[8][GSTR];  // As[k2][m]  half2(k, k+1)
    __shared__ uint32_t Bs[8][GSTR];  // Bs[k2][n]  half2(row k, row k+1)

    const int K = Cn;
    const int N = 3 * Cn;

    int tid  = threadIdx.x;
    int lane = tid & 31;
    int wid  = tid >> 5;
    int warpM = wid >> 2;
    int warpN = wid & 3;
    int rq = lane >> 2;
    int cj = lane & 3;
    int bm = blockIdx.y * 128;
    int bn = blockIdx.x * 128;

    int arow = tid >> 1;
    int akq2 = (tid & 1) * 4;
    const float* aPtr = x + (size_t)(bm + arow) * K + (tid & 1) * 8;

    int bk2 = tid >> 5;          // 0..7
    int bnq = (tid & 31) * 4;

    float4 aReg[2], bReg[2];
    aReg[0] = *(const float4*)(aPtr);
    aReg[1] = *(const float4*)(aPtr + 4);
    bReg[0] = *(const float4*)&w[(size_t)(2 * bk2) * N + bn + bnq];
    bReg[1] = *(const float4*)&w[(size_t)(2 * bk2 + 1) * N + bn + bnq];

    float acc[4][4][4];
    #pragma unroll
    for (int i = 0; i < 4; i++)
        #pragma unroll
        for (int j = 0; j < 4; j++)
            #pragma unroll
            for (int r = 0; r < 4; r++) acc[i][j][r] = 0.f;

    for (int k0 = 0; k0 < K; k0 += 16) {
        __syncthreads();
        As[akq2 + 0][arow] = f2h2(aReg[0].x, aReg[0].y);
        As[akq2 + 1][arow] = f2h2(aReg[0].z, aReg[0].w);
        As[akq2 + 2][arow] = f2h2(aReg[1].x, aReg[1].y);
        As[akq2 + 3][arow] = f2h2(aReg[1].z, aReg[1].w);
        {
            uint4 bu;
            bu.x = f2h2(bReg[0].x, bReg[1].x);
            bu.y = f2h2(bReg[0].y, bReg[1].y);
            bu.z = f2h2(bReg[0].z, bReg[1].z);
            bu.w = f2h2(bReg[0].w, bReg[1].w);
            *(uint4*)&Bs[bk2][bnq] = bu;
        }
        __syncthreads();

        if (k0 + 16 < K) {
            aReg[0] = *(const float4*)(aPtr + k0 + 16);
            aReg[1] = *(const float4*)(aPtr + k0 + 20);
            bReg[0] = *(const float4*)&w[(size_t)(k0 + 16 + 2 * bk2) * N + bn + bnq];
            bReg[1] = *(const float4*)&w[(size_t)(k0 + 17 + 2 * bk2) * N + bn + bnq];
        }

        uint32_t a[4][4], b[4][2];
        #pragma unroll
        for (int mf = 0; mf < 4; mf++) {
            int m = warpM * 64 + mf * 16 + rq;
            a[mf][0] = As[cj][m];
            a[mf][1] = As[cj][m + 8];
            a[mf][2] = As[cj + 4][m];
            a[mf][3] = As[cj + 4][m + 8];
        }
        #pragma unroll
        for (int nf = 0; nf < 4; nf++) {
            int n = warpN * 32 + nf * 8 + rq;
            b[nf][0] = Bs[cj][n];
            b[nf][1] = Bs[cj + 4][n];
        }
        #pragma unroll
        for (int mf = 0; mf < 4; mf++)
            #pragma unroll
            for (int nf = 0; nf < 4; nf++)
                mma_f16(acc[mf][nf], a[mf], b[nf]);
    }

    #pragma unroll
    for (int mf = 0; mf < 4; mf++) {
        #pragma unroll
        for (int nf = 0; nf < 4; nf++) {
            #pragma unroll
            for (int r = 0; r < 4; r++) {
                int m = bm + warpM * 64 + mf * 16 + rq + (r >> 1) * 8;
                int n = bn + warpN * 32 + nf * 8 + cj * 2 + (r & 1);
                float val = acc[mf][nf][r] + bias[n];
                int b2 = m >> 11;
                int t = m & 2047;
                int sec = n >> 10;
                int c = n & 1023;
                int h = c >> 6;
                int d = c & 63;
                if (sec == 0) {
                    g_q[(((size_t)b2 * Hn + h) * Tn + t) * Dn + d] = val;
                } else if (sec == 1) {
                    g_k[(((size_t)b2 * Hn + h) * Tn + t) * Dn + d] =
                        __uint_as_float(f2tf32(val));
                } else {
                    g_v[(((size_t)b2 * Hn + h) * Dn + d) * Tn + t] =
                        __uint_as_float(f2tf32(val));
                }
            }
        }
    }
}

// ---------------------------------------------------------------------------
// GEMM 2 (fp16 tensor core): out = g_y @ w_proj + b_proj -> [8192, 1024]
// ---------------------------------------------------------------------------
__global__ __launch_bounds__(256) void proj_gemm_kernel(
    const float* __restrict__ w,
    const float* __restrict__ bias,
    float* __restrict__ out)
{
    __shared__ uint32_t As[8][GSTR];
    __shared__ uint32_t Bs[8][GSTR];

    const int K = Cn;
    const int N = Cn;

    int tid  = threadIdx.x;
    int lane = tid & 31;
    int wid  = tid >> 5;
    int warpM = wid >> 2;
    int warpN = wid & 3;
    int rq = lane >> 2;
    int cj = lane & 3;
    int bm = blockIdx.y * 128;
    int bn = blockIdx.x * 128;

    int arow = tid >> 1;
    int akq2 = (tid & 1) * 4;
    const float* aPtr = g_y + (size_t)(bm + arow) * K + (tid & 1) * 8;

    int bk2 = tid >> 5;
    int bnq = (tid & 31) * 4;

    float4 aReg[2], bReg[2];
    aReg[0] = *(const float4*)(aPtr);
    aReg[1] = *(const float4*)(aPtr + 4);
    bReg[0] = *(const float4*)&w[(size_t)(2 * bk2) * N + bn + bnq];
    bReg[1] = *(const float4*)&w[(size_t)(2 * bk2 + 1) * N + bn + bnq];

    float acc[4][4][4];
    #pragma unroll
    for (int i = 0; i < 4; i++)
        #pragma unroll
        for (int j = 0; j < 4; j++)
            #pragma unroll
            for (int r = 0; r < 4; r++) acc[i][j][r] = 0.f;

    for (int k0 = 0; k0 < K; k0 += 16) {
        __syncthreads();
        As[akq2 + 0][arow] = f2h2(aReg[0].x, aReg[0].y);
        As[akq2 + 1][arow] = f2h2(aReg[0].z, aReg[0].w);
        As[akq2 + 2][arow] = f2h2(aReg[1].x, aReg[1].y);
        As[akq2 + 3][arow] = f2h2(aReg[1].z, aReg[1].w);
        {
            uint4 bu;
            bu.x = f2h2(bReg[0].x, bReg[1].x);
            bu.y = f2h2(bReg[0].y, bReg[1].y);
            bu.z = f2h2(bReg[0].z, bReg[1].z);
            bu.w = f2h2(bReg[0].w, bReg[1].w);
            *(uint4*)&Bs[bk2][bnq] = bu;
        }
        __syncthreads();

        if (k0 + 16 < K) {
            aReg[0] = *(const float4*)(aPtr + k0 + 16);
            aReg[1] = *(const float4*)(aPtr + k0 + 20);
            bReg[0] = *(const float4*)&w[(size_t)(k0 + 16 + 2 * bk2) * N + bn + bnq];
            bReg[1] = *(const float4*)&w[(size_t)(k0 + 17 + 2 * bk2) * N + bn + bnq];
        }

        uint32_t a[4][4], b[4][2];
        #pragma unroll
        for (int mf = 0; mf < 4; mf++) {
            int m = warpM * 64 + mf * 16 + rq;
            a[mf][0] = As[cj][m];
            a[mf][1] = As[cj][m + 8];
            a[mf][2] = As[cj + 4][m];
            a[mf][3] = As[cj + 4][m + 8];
        }
        #pragma unroll
        for (int nf = 0; nf < 4; nf++) {
            int n = warpN * 32 + nf * 8 + rq;
            b[nf][0] = Bs[cj][n];
            b[nf][1] = Bs[cj + 4][n];
        }
        #pragma unroll
        for (int mf = 0; mf < 4; mf++)
            #pragma unroll
            for (int nf = 0; nf < 4; nf++)
                mma_f16(acc[mf][nf], a[mf], b[nf]);
    }

    #pragma unroll
    for (int mf = 0; mf < 4; mf++) {
        #pragma unroll
        for (int nf = 0; nf < 4; nf++) {
            int n = bn + warpN * 32 + nf * 8 + cj * 2;
            float bx = bias[n], by = bias[n + 1];
            #pragma unroll
            for (int half = 0; half < 2; half++) {
                int m = bm + warpM * 64 + mf * 16 + rq + half * 8;
                float2 v2;
                v2.x = acc[mf][nf][half * 2 + 0] + bx;
                v2.y = acc[mf][nf][half * 2 + 1] + by;
                *(float2*)&out[(size_t)m * N + n] = v2;
            }
        }
    }
}

// ---------------------------------------------------------------------------
// Flash attention, tf32 tensor cores, Q register-resident. (unchanged R5)
// ---------------------------------------------------------------------------
#define AKS 68
#define APS 36

__global__ __launch_bounds__(128) void attn_kernel()
{
    __shared__ uint32_t Ks[32 * AKS];
    __shared__ uint32_t Vt[64 * APS];
    __shared__ uint32_t Ps[128 * APS];

    int tid  = threadIdx.x;
    int lane = tid & 31;
    int w    = tid >> 5;
    int bh = blockIdx.y;
    int qt = blockIdx.x;
    int q0 = qt * 128;

    const float* qptr = g_q + (size_t)bh * Tn * Dn;
    const uint32_t* kptr = (const uint32_t*)(g_k) + (size_t)bh * Tn * Dn;
    const uint32_t* vtptr = (const uint32_t*)(g_v) + (size_t)bh * Dn * Tn;

    const int rq = lane >> 2;
    const int cj = lane & 3;
    const int qrow = w * 32;

    uint32_t qa[8][2][4];
    #pragma unroll
    for (int kk = 0; kk < 8; kk++) {
        int kc = kk * 8 + cj;
        #pragma unroll
        for (int mf = 0; mf < 2; mf++) {
            const float* qr = qptr + (size_t)(q0 + qrow + mf * 16 + rq) * Dn;
            qa[kk][mf][0] = f2tf32(qr[kc] * 0.125f);
            qa[kk][mf][1] = f2tf32(qr[8 * Dn + kc] * 0.125f);
            qa[kk][mf][2] = f2tf32(qr[kc + 4] * 0.125f);
            qa[kk][mf][3] = f2tf32(qr[8 * Dn + kc + 4] * 0.125f);
        }
    }

    float m_i[2][2], l_i[2][2];
    float o[2][8][4];
    #pragma unroll
    for (int mf = 0; mf < 2; mf++) {
        m_i[mf][0] = -1e30f; m_i[mf][1] = -1e30f;
        l_i[mf][0] = 0.f;    l_i[mf][1] = 0.f;
        #pragma unroll
        for (int nf = 0; nf < 8; nf++)
            #pragma unroll
            for (int r = 0; r < 4; r++) o[mf][nf][r] = 0.f;
    }

    const int n_ktiles = 4 * qt + 4;

    for (int kt = 0; kt < n_ktiles; kt++) {
        int k0 = kt * 32;
        __syncthreads();

        {
            int r  = tid >> 2;
            int cb = (tid & 3) * 16;
            const uint32_t* src = kptr + (size_t)(k0 + r) * Dn + cb;
            #pragma unroll
            for (int u = 0; u < 4; u++)
                *(uint4*)&Ks[r * AKS + cb + u * 4] = *(const uint4*)(src + u * 4);
        }
        {
            int r  = tid >> 1;
            int cb = (tid & 1) * 16;
            const uint32_t* src = vtptr + (size_t)r * Tn + k0 + cb;
            #pragma unroll
            for (int u = 0; u < 4; u++)
                *(uint4*)&Vt[r * APS + cb + u * 4] = *(const uint4*)(src + u * 4);
        }
        __syncthreads();

        float s[2][4][4];
        #pragma unroll
        for (int mf = 0; mf < 2; mf++)
            #pragma unroll
            for (int nf = 0; nf < 4; nf++)
                #pragma unroll
                for (int r = 0; r < 4; r++) s[mf][nf][r] = 0.f;

        #pragma unroll
        for (int kk = 0; kk < 8; kk++) {
            int kc = kk * 8;
            #pragma unroll
            for (int nf = 0; nf < 4; nf++) {
                uint32_t b[2];
                b[0] = Ks[(nf * 8 + rq) * AKS + kc + cj];
                b[1] = Ks[(nf * 8 + rq) * AKS + kc + cj + 4];
                mma_tf32(s[0][nf], qa[kk][0], b);
                mma_tf32(s[1][nf], qa[kk][1], b);
            }
        }

        #pragma unroll
        for (int mf = 0; mf < 2; mf++) {
            int rowA = q0 + qrow + mf * 16 + rq;
            int rowB = rowA + 8;
            if (k0 + 31 > q0 + qrow + mf * 16) {
                #pragma unroll
                for (int nf = 0; nf < 4; nf++) {
                    int col = k0 + nf * 8 + cj * 2;
                    if (col > rowA)     s[mf][nf][0] = -1e30f;
                    if (col + 1 > rowA) s[mf][nf][1] = -1e30f;
                    if (col > rowB)     s[mf][nf][2] = -1e30f;
                    if (col + 1 > rowB) s[mf][nf][3] = -1e30f;
                }
            }
        }

        #pragma unroll
        for (int mf = 0; mf < 2; mf++) {
            float mtA = fmaxf(fmaxf(s[mf][0][0], s[mf][0][1]),
                              fmaxf(s[mf][1][0], s[mf][1][1]));
            mtA = fmaxf(mtA, fmaxf(fmaxf(s[mf][2][0], s[mf][2][1]),
                                   fmaxf(s[mf][3][0], s[mf][3][1])));
            float mtB = fmaxf(fmaxf(s[mf][0][2], s[mf][0][3]),
                              fmaxf(s[mf][1][2], s[mf][1][3]));
            mtB = fmaxf(mtB, fmaxf(fmaxf(s[mf][2][2], s[mf][2][3]),
                                   fmaxf(s[mf][3][2], s[mf][3][3])));
            #pragma unroll
            for (int off = 1; off < 4; off <<= 1) {
                mtA = fmaxf(mtA, __shfl_xor_sync(0xffffffffu, mtA, off));
                mtB = fmaxf(mtB, __shfl_xor_sync(0xffffffffu, mtB, off));
            }
            float mnA = fmaxf(m_i[mf][0], mtA);
            float mnB = fmaxf(m_i[mf][1], mtB);
            float fA = __expf(m_i[mf][0] - mnA);
            float fB = __expf(m_i[mf][1] - mnB);
            m_i[mf][0] = mnA; m_i[mf][1] = mnB;

            float rsA = 0.f, rsB = 0.f;
            #pragma unroll
            for (int nf = 0; nf < 4; nf++) {
                s[mf][nf][0] = __expf(s[mf][nf][0] - mnA);
                s[mf][nf][1] = __expf(s[mf][nf][1] - mnA);
                s[mf][nf][2] = __expf(s[mf][nf][2] - mnB);
                s[mf][nf][3] = __expf(s[mf][nf][3] - mnB);
                rsA += s[mf][nf][0] + s[mf][nf][1];
                rsB += s[mf][nf][2] + s[mf][nf][3];
            }
            #pragma unroll
            for (int off = 1; off < 4; off <<= 1) {
                rsA += __shfl_xor_sync(0xffffffffu, rsA, off);
                rsB += __shfl_xor_sync(0xffffffffu, rsB, off);
            }
            l_i[mf][0] = l_i[mf][0] * fA + rsA;
            l_i[mf][1] = l_i[mf][1] * fB + rsB;
            #pragma unroll
            for (int nf = 0; nf < 8; nf++) {
                o[mf][nf][0] *= fA; o[mf][nf][1] *= fA;
                o[mf][nf][2] *= fB; o[mf][nf][3] *= fB;
            }
        }

        #pragma unroll
        for (int mf = 0; mf < 2; mf++) {
            int rA = qrow + mf * 16 + rq;
            #pragma unroll
            for (int nf = 0; nf < 4; nf++) {
                int col = nf * 8 + cj * 2;
                Ps[rA * APS + col]           = f2tf32(s[mf][nf][0]);
                Ps[rA * APS + col + 1]       = f2tf32(s[mf][nf][1]);
                Ps[(rA + 8) * APS + col]     = f2tf32(s[mf][nf][2]);
                Ps[(rA + 8) * APS + col + 1] = f2tf32(s[mf][nf][3]);
            }
        }
        __syncwarp();

        #pragma unroll
        for (int kk = 0; kk < 4; kk++) {
            int kc = kk * 8;
            uint32_t a[2][4];
            #pragma unroll
            for (int mf = 0; mf < 2; mf++) {
                int rA = qrow + mf * 16 + rq;
                a[mf][0] = Ps[rA * APS + kc + cj];
                a[mf][1] = Ps[(rA + 8) * APS + kc + cj];
                a[mf][2] = Ps[rA * APS + kc + cj + 4];
                a[mf][3] = Ps[(rA + 8) * APS + kc + cj + 4];
            }
            #pragma unroll
            for (int nf = 0; nf < 8; nf++) {
                uint32_t b[2];
                b[0] = Vt[(nf * 8 + rq) * APS + kc + cj];
                b[1] = Vt[(nf * 8 + rq) * APS + kc + cj + 4];
                mma_tf32(o[0][nf], a[0], b);
                mma_tf32(o[1][nf], a[1], b);
            }
        }
        __syncwarp();
    }

    int b = bh >> 4;
    int h = bh & 15;
    #pragma unroll
    for (int mf = 0; mf < 2; mf++) {
        float invA = 1.f / l_i[mf][0];
        float invB = 1.f / l_i[mf][1];
        int tA = q0 + qrow + mf * 16 + rq;
        int tB = tA + 8;
        #pragma unroll
        for (int nf = 0; nf < 8; nf++) {
            int d = h * Dn + nf * 8 + cj * 2;
            float2 vA = make_float2(o[mf][nf][0] * invA, o[mf][nf][1] * invA);
            float2 vB = make_float2(o[mf][nf][2] * invB, o[mf][nf][3] * invB);
            *(float2*)&g_y[((size_t)(b * Tn + tA)) * Cn + d] = vA;
            *(float2*)&g_y[((size_t)(b * Tn + tB)) * Cn + d] = vB;
        }
    }
}

// ---------------------------------------------------------------------------
// Launch: kernel launches ONLY.
// ---------------------------------------------------------------------------
extern "C" void kernel_launch(void* const* d_in, const int* in_sizes, int n_in,
                              void* d_out, int out_size)
{
    const float* x      = (const float*)d_in[0];
    const float* w_attn = (const float*)d_in[1];
    const float* b_attn = (const float*)d_in[2];
    const float* w_proj = (const float*)d_in[3];
    const float* b_proj = (const float*)d_in[4];
    float* out = (float*)d_out;

    {
        dim3 grid(3 * Cn / 128, Mrows / 128);
        qkv_gemm_kernel<<<grid, 256>>>(x, w_attn, b_attn);
    }
    {
        dim3 grid(Tn / 128, Bn * Hn);
        attn_kernel<<<grid, 128>>>();
    }
    {
        dim3 grid(Cn / 128, Mrows / 128);
        proj_gemm_kernel<<<grid, 256>>>(w_proj, b_proj, out);
    }
}